// round 1
// baseline (speedup 1.0000x reference)
#include <cuda_runtime.h>
#include <math.h>

#define TT 256
#define BB 64
#define II 256
#define HH 256
#define NN 8
#define FF 1024   // 4*H

// Scratch: precomputed x-path pre-activations ZX[t][n][b][f]  (512 MB)
__device__ float g_zx[(size_t)TT * NN * BB * FF];
// Cell state c[n][b][h] (512 KB). Written before read at every t (t==0 reads 0 const).
__device__ float g_c[NN * BB * HH];

// ---------------------------------------------------------------------------
// Kernel 1: ZX[t,n,b,f] = sum_i x[t,b,i] * W[n,i,f] + bias_i[n,f] + bias_h[n,f]
// Tiled 64x64 fp32 GEMM. grid = (T*B/64, FF/64, N), 256 threads.
// ---------------------------------------------------------------------------
__global__ __launch_bounds__(256) void zx_kernel(
    const float* __restrict__ x,    // [T*B, I]
    const float* __restrict__ w,    // [N, I+H, FF]
    const float* __restrict__ bi,   // [N, FF]
    const float* __restrict__ bh)   // [N, FF]
{
    const int mt = blockIdx.x;
    const int ft = blockIdx.y;
    const int n  = blockIdx.z;

    __shared__ float As[32][65];  // [k][m], padded
    __shared__ float Bs[32][64];  // [k][f]

    const int tid = threadIdx.x;
    const int tx = tid & 15;      // column group within tile
    const int ty = tid >> 4;      // row group

    float acc[4][4];
#pragma unroll
    for (int r = 0; r < 4; r++)
#pragma unroll
        for (int g = 0; g < 4; g++) acc[r][g] = 0.f;

    const float* wbase = w + (size_t)n * (II + HH) * FF + (size_t)ft * 64;

    for (int kk = 0; kk < II; kk += 32) {
        // Load A tile (64 rows x 32 k), store transposed As[k][m]
        {
            const int k  = tid & 31;
            const int m0 = tid >> 5;
#pragma unroll
            for (int p = 0; p < 8; p++) {
                const int m = m0 + p * 8;
                As[k][m] = x[(size_t)(mt * 64 + m) * II + kk + k];
            }
        }
        // Load B tile (32 k x 64 f)
        {
            const int f  = tid & 63;
            const int k0 = tid >> 6;
#pragma unroll
            for (int p = 0; p < 8; p++) {
                const int k = k0 + p * 4;
                Bs[k][f] = wbase[(size_t)(kk + k) * FF + f];
            }
        }
        __syncthreads();
#pragma unroll
        for (int k = 0; k < 32; k++) {
            float a0 = As[k][ty],      a1 = As[k][ty + 16],
                  a2 = As[k][ty + 32], a3 = As[k][ty + 48];
            float b0 = Bs[k][tx],      b1 = Bs[k][tx + 16],
                  b2 = Bs[k][tx + 32], b3 = Bs[k][tx + 48];
            acc[0][0] += a0 * b0; acc[0][1] += a0 * b1; acc[0][2] += a0 * b2; acc[0][3] += a0 * b3;
            acc[1][0] += a1 * b0; acc[1][1] += a1 * b1; acc[1][2] += a1 * b2; acc[1][3] += a1 * b3;
            acc[2][0] += a2 * b0; acc[2][1] += a2 * b1; acc[2][2] += a2 * b2; acc[2][3] += a2 * b3;
            acc[3][0] += a3 * b0; acc[3][1] += a3 * b1; acc[3][2] += a3 * b2; acc[3][3] += a3 * b3;
        }
        __syncthreads();
    }

    // Epilogue: add bias, scatter to ZX[t,n,b,f]
    float bias[4];
#pragma unroll
    for (int g = 0; g < 4; g++) {
        const int f = ft * 64 + tx + 16 * g;
        bias[g] = bi[n * FF + f] + bh[n * FF + f];
    }
#pragma unroll
    for (int r = 0; r < 4; r++) {
        const int m = mt * 64 + ty + 16 * r;   // m = t*B + b
        const int t = m >> 6;
        const int b = m & 63;
        float* zrow = g_zx + ((size_t)(t * NN + n) * BB + b) * FF + ft * 64;
#pragma unroll
        for (int g = 0; g < 4; g++)
            zrow[tx + 16 * g] = acc[r][g] + bias[g];
    }
}

// ---------------------------------------------------------------------------
// Kernel 2: one time step.
// grid = (H/16 = 16, N = 8) = 128 CTAs, 256 threads.
// CTA (jt, n) computes z[b, {gate*H + jt*16 + j}] = h_prev @ Wh + ZX, then
// the full LSTM gate/cell/mask epilogue for h-columns [jt*16, jt*16+16).
// Thread (tx,ty): h-col j = jt*16+tx; rows b = ty + 16*r; 4 accumulator
// columns = the 4 gates of column j (no cross-thread exchange needed).
// ---------------------------------------------------------------------------
__global__ __launch_bounds__(256) void step_kernel(
    const float* __restrict__ w,    // [N, I+H, FF]
    const int*   __restrict__ fd,   // [T*B]
    float*       __restrict__ out,  // [T, N, B, H]
    int t)
{
    const int jt = blockIdx.x;
    const int n  = blockIdx.y;

    __shared__ float Hs[32][65];  // [k][b], padded
    __shared__ float Ws[32][64];  // [k][c]

    const int tid = threadIdx.x;
    const int tx = tid & 15;
    const int ty = tid >> 4;

    float acc[4][4];
#pragma unroll
    for (int r = 0; r < 4; r++)
#pragma unroll
        for (int g = 0; g < 4; g++) acc[r][g] = 0.f;

    const float* hprev = out + ((size_t)((t - 1) * NN + n) * BB) * HH;  // valid when t>0
    const float* wbase = w + (size_t)n * (II + HH) * FF + (size_t)II * FF;  // Wh part

    for (int kk = 0; kk < HH; kk += 32) {
        // Load h_prev tile (64 b x 32 k) -> Hs[k][b]
        {
            const int k  = tid & 31;
            const int b0 = tid >> 5;
#pragma unroll
            for (int p = 0; p < 8; p++) {
                const int b = b0 + p * 8;
                Hs[k][b] = (t == 0) ? 0.f : hprev[(size_t)b * HH + kk + k];
            }
        }
        // Load Wh tile (32 k x 64 c); column c maps to f = (c>>4)*H + jt*16 + (c&15)
        {
            const int c  = tid & 63;
            const int k0 = tid >> 6;
            const int f  = (c >> 4) * HH + jt * 16 + (c & 15);
#pragma unroll
            for (int p = 0; p < 8; p++) {
                const int k = k0 + p * 4;
                Ws[k][c] = wbase[(size_t)(kk + k) * FF + f];
            }
        }
        __syncthreads();
#pragma unroll
        for (int k = 0; k < 32; k++) {
            float a0 = Hs[k][ty],      a1 = Hs[k][ty + 16],
                  a2 = Hs[k][ty + 32], a3 = Hs[k][ty + 48];
            float b0 = Ws[k][tx],      b1 = Ws[k][tx + 16],
                  b2 = Ws[k][tx + 32], b3 = Ws[k][tx + 48];
            acc[0][0] += a0 * b0; acc[0][1] += a0 * b1; acc[0][2] += a0 * b2; acc[0][3] += a0 * b3;
            acc[1][0] += a1 * b0; acc[1][1] += a1 * b1; acc[1][2] += a1 * b2; acc[1][3] += a1 * b3;
            acc[2][0] += a2 * b0; acc[2][1] += a2 * b1; acc[2][2] += a2 * b2; acc[2][3] += a2 * b3;
            acc[3][0] += a3 * b0; acc[3][1] += a3 * b1; acc[3][2] += a3 * b2; acc[3][3] += a3 * b3;
        }
        __syncthreads();
    }

    // LSTM epilogue
    const int j = jt * 16 + tx;
    const float* zxb = g_zx + ((size_t)(t * NN + n) * BB) * FF;
#pragma unroll
    for (int r = 0; r < 4; r++) {
        const int b = ty + 16 * r;
        const float* zrow = zxb + (size_t)b * FF;
        const float zi = acc[r][0] + zrow[0 * HH + j];
        const float zf = acc[r][1] + zrow[1 * HH + j];
        const float zo = acc[r][2] + zrow[2 * HH + j];
        const float zg = acc[r][3] + zrow[3 * HH + j];

        const int dur  = fd[t * BB + b];
        const bool keep = (n > (dur >> 3));     // branch_idx > dur // RESCALE_RATE

        const int cidx = (n * BB + b) * HH + j;
        const float cold = (t == 0) ? 0.f : g_c[cidx];

        const float ig = 1.f / (1.f + expf(-zi));
        const float fg = 1.f / (1.f + expf(-zf));
        const float og = 1.f / (1.f + expf(-zo));
        const float gg = tanhf(zg);

        float cn = fg * cold + ig * gg;
        cn = keep ? cold : cn;
        const float hn = og * tanhf(cn);

        out[((size_t)(t * NN + n) * BB + b) * HH + j] = hn;
        g_c[cidx] = cn;
    }
}

// ---------------------------------------------------------------------------
extern "C" void kernel_launch(void* const* d_in, const int* in_sizes, int n_in,
                              void* d_out, int out_size)
{
    const float* x  = (const float*)d_in[0];   // [T,B,I] f32
    const int*   fd = (const int*)  d_in[1];   // [T,B]   i32
    const float* w  = (const float*)d_in[2];   // [N,I+H,4H] f32
    const float* bi = (const float*)d_in[3];   // [N,4H]
    const float* bh = (const float*)d_in[4];   // [N,4H]
    float* out = (float*)d_out;                // [T,N,B,H]

    dim3 zgrid(TT * BB / 64, FF / 64, NN);     // 256 x 16 x 8
    zx_kernel<<<zgrid, 256>>>(x, w, bi, bh);

    dim3 sgrid(HH / 16, NN);                   // 16 x 8 = 128 CTAs
    for (int t = 0; t < TT; t++)
        step_kernel<<<sgrid, 256>>>(w, fd, out, t);
}

// round 2
// speedup vs baseline: 1.2967x; 1.2967x over previous
#include <cuda_runtime.h>
#include <math.h>

#define TT 256
#define BB 64
#define II 256
#define HH 256
#define NN 8
#define FF 1024   // 4*H

// Scratch: precomputed x-path pre-activations ZX[t][n][b][f]  (512 MB)
__device__ float g_zx[(size_t)TT * NN * BB * FF];
// Per-(t,n) arrival flags for the persistent recurrence (zeroed by zx_kernel each run)
__device__ int g_flags[TT * NN];

// ---------------------------------------------------------------------------
// Kernel 1: ZX[t,n,b,f] = sum_i x[t,b,i] * W[n,i,f] + bias_i[n,f] + bias_h[n,f]
// Tiled 64x64 fp32 GEMM. grid = (T*B/64, FF/64, N), 256 threads.
// Also zeroes g_flags (runs before the persistent kernel on the same stream).
// ---------------------------------------------------------------------------
__global__ __launch_bounds__(256) void zx_kernel(
    const float* __restrict__ x,    // [T*B, I]
    const float* __restrict__ w,    // [N, I+H, FF]
    const float* __restrict__ bi,   // [N, FF]
    const float* __restrict__ bh)   // [N, FF]
{
    const int mt = blockIdx.x;
    const int ft = blockIdx.y;
    const int n  = blockIdx.z;
    const int tid = threadIdx.x;

    // zero the flags (T*N = 2048 = 8 CTAs x 256 threads)
    if (ft == 0 && n == 0 && mt < 8) g_flags[mt * 256 + tid] = 0;

    __shared__ float As[32][65];  // [k][m], padded
    __shared__ float Bs[32][64];  // [k][f]

    const int tx = tid & 15;      // column group within tile
    const int ty = tid >> 4;      // row group

    float acc[4][4];
#pragma unroll
    for (int r = 0; r < 4; r++)
#pragma unroll
        for (int g = 0; g < 4; g++) acc[r][g] = 0.f;

    const float* wbase = w + (size_t)n * (II + HH) * FF + (size_t)ft * 64;

    for (int kk = 0; kk < II; kk += 32) {
        {
            const int k  = tid & 31;
            const int m0 = tid >> 5;
#pragma unroll
            for (int p = 0; p < 8; p++) {
                const int m = m0 + p * 8;
                As[k][m] = x[(size_t)(mt * 64 + m) * II + kk + k];
            }
        }
        {
            const int f  = tid & 63;
            const int k0 = tid >> 6;
#pragma unroll
            for (int p = 0; p < 8; p++) {
                const int k = k0 + p * 4;
                Bs[k][f] = wbase[(size_t)(kk + k) * FF + f];
            }
        }
        __syncthreads();
#pragma unroll
        for (int k = 0; k < 32; k++) {
            float a0 = As[k][ty],      a1 = As[k][ty + 16],
                  a2 = As[k][ty + 32], a3 = As[k][ty + 48];
            float b0 = Bs[k][tx],      b1 = Bs[k][tx + 16],
                  b2 = Bs[k][tx + 32], b3 = Bs[k][tx + 48];
            acc[0][0] += a0 * b0; acc[0][1] += a0 * b1; acc[0][2] += a0 * b2; acc[0][3] += a0 * b3;
            acc[1][0] += a1 * b0; acc[1][1] += a1 * b1; acc[1][2] += a1 * b2; acc[1][3] += a1 * b3;
            acc[2][0] += a2 * b0; acc[2][1] += a2 * b1; acc[2][2] += a2 * b2; acc[2][3] += a2 * b3;
            acc[3][0] += a3 * b0; acc[3][1] += a3 * b1; acc[3][2] += a3 * b2; acc[3][3] += a3 * b3;
        }
        __syncthreads();
    }

    float bias[4];
#pragma unroll
    for (int g = 0; g < 4; g++) {
        const int f = ft * 64 + tx + 16 * g;
        bias[g] = bi[n * FF + f] + bh[n * FF + f];
    }
#pragma unroll
    for (int r = 0; r < 4; r++) {
        const int m = mt * 64 + ty + 16 * r;   // m = t*B + b
        const int t = m >> 6;
        const int b = m & 63;
        float* zrow = g_zx + ((size_t)(t * NN + n) * BB + b) * FF + ft * 64;
#pragma unroll
        for (int g = 0; g < 4; g++)
            zrow[tx + 16 * g] = acc[r][g] + bias[g];
    }
}

// ---------------------------------------------------------------------------
// Kernel 2: persistent recurrence. grid = 128 CTAs (all co-resident), 256 thr.
// CTA (jt, n): owns h-columns [jt*16, jt*16+16) of branch n for ALL t.
//   - Wh slice [256 k][64 c] resident in SMEM for the whole kernel
//     (column c -> f = (c>>4)*H + jt*16 + (c&15): 4 gates x 16 h-cols)
//   - cell state lives in registers (4 floats per thread)
//   - per step: cp.async prefetch of the ZX tile overlapped with a spin on
//     the per-(t-1, n) flag; h tile loaded from `out` (L2); FFMA GEMM;
//     thread-local LSTM epilogue; release-arrive on flag[t][n].
// ---------------------------------------------------------------------------
__global__ __launch_bounds__(256, 1) void recur_kernel(
    const float* __restrict__ w,    // [N, I+H, FF]
    const int*   __restrict__ fd,   // [T*B]
    float* out)                     // [T, N, B, H]
{
    extern __shared__ float smem[];
    float* Ws  = smem;                  // [256][64]  64 KB
    float* Hs  = smem + 256 * 64;       // [256][64]  64 KB
    float* ZXs = smem + 2 * 256 * 64;   // [64][64]   16 KB

    const int jt = blockIdx.x & 15;
    const int n  = blockIdx.x >> 4;
    const int tid = threadIdx.x;
    const int tx = tid & 15;
    const int ty = tid >> 4;

    // ---- load Wh slice into SMEM once ----
    const float* wbase = w + (size_t)n * (II + HH) * FF + (size_t)II * FF;
    for (int i = tid; i < 256 * 64; i += 256) {
        const int k = i >> 6, c = i & 63;
        Ws[i] = wbase[(size_t)k * FF + (c >> 4) * HH + jt * 16 + (c & 15)];
    }

    // zx prefetch mapping: thread -> (b = tid>>2, g = tid&3), copies 16 floats
    const int zb = tid >> 2;
    const int zg = tid & 3;
    const unsigned zxs_dst = (unsigned)__cvta_generic_to_shared(ZXs + zb * 64 + zg * 16);

    // h load mapping: thread -> row b_ld, k-chunk kc (64 k each)
    const int b_ld = tid & 63;
    const int kc   = tid >> 6;

    // cell state registers: rows ty, ty+16, ty+32, ty+48; column jt*16+tx
    float creg[4] = {0.f, 0.f, 0.f, 0.f};

    const int j = jt * 16 + tx;

    for (int t = 0; t < TT; t++) {
        // -- issue ZX prefetch for this step (overlaps the spin below) --
        {
            const float* zsrc = g_zx + ((size_t)(t * NN + n) * BB + zb) * FF
                                + zg * HH + jt * 16;
#pragma unroll
            for (int q = 0; q < 4; q++) {
                asm volatile("cp.async.ca.shared.global [%0], [%1], 16;\n"
                             :: "r"(zxs_dst + q * 16), "l"(zsrc + q * 4));
            }
            asm volatile("cp.async.commit_group;\n");
        }

        if (t > 0) {
            // -- wait for all 16 CTAs of branch n to publish h(t-1) --
            if (tid == 0) {
                int v;
                do {
                    asm volatile("ld.acquire.gpu.global.s32 %0, [%1];"
                                 : "=r"(v) : "l"(g_flags + (t - 1) * NN + n));
                } while (v < 16);
            }
            __syncthreads();   // propagate acquire to whole CTA

            // -- load h(t-1) tile [64 b][256 k] -> Hs[k][b] --
            const float* hrow = out + ((size_t)((t - 1) * NN + n) * BB + b_ld) * HH
                                + kc * 64;
#pragma unroll
            for (int i = 0; i < 16; i++) {
                const float4 v = *(const float4*)(hrow + i * 4);
                const int k = kc * 64 + i * 4;
                Hs[(k + 0) * 64 + b_ld] = v.x;
                Hs[(k + 1) * 64 + b_ld] = v.y;
                Hs[(k + 2) * 64 + b_ld] = v.z;
                Hs[(k + 3) * 64 + b_ld] = v.w;
            }
        }

        asm volatile("cp.async.wait_group 0;\n");
        __syncthreads();

        // -- GEMM: acc[r][g] = sum_k h[b=ty+16r][k] * Wh[k][g*16+tx] --
        float acc[4][4];
#pragma unroll
        for (int r = 0; r < 4; r++)
#pragma unroll
            for (int g = 0; g < 4; g++) acc[r][g] = 0.f;

        if (t > 0) {
#pragma unroll 8
            for (int k = 0; k < 256; k++) {
                const float* hk = Hs + k * 64;
                const float* wk = Ws + k * 64;
                const float a0 = hk[ty],      a1 = hk[ty + 16],
                            a2 = hk[ty + 32], a3 = hk[ty + 48];
                const float b0 = wk[tx],      b1 = wk[tx + 16],
                            b2 = wk[tx + 32], b3 = wk[tx + 48];
                acc[0][0] += a0 * b0; acc[0][1] += a0 * b1; acc[0][2] += a0 * b2; acc[0][3] += a0 * b3;
                acc[1][0] += a1 * b0; acc[1][1] += a1 * b1; acc[1][2] += a1 * b2; acc[1][3] += a1 * b3;
                acc[2][0] += a2 * b0; acc[2][1] += a2 * b1; acc[2][2] += a2 * b2; acc[2][3] += a2 * b3;
                acc[3][0] += a3 * b0; acc[3][1] += a3 * b1; acc[3][2] += a3 * b2; acc[3][3] += a3 * b3;
            }
        }

        // -- LSTM epilogue (all data thread-local / SMEM) --
#pragma unroll
        for (int r = 0; r < 4; r++) {
            const int b = ty + 16 * r;
            const float* zrow = ZXs + b * 64;
            const float zi = acc[r][0] + zrow[tx];
            const float zf = acc[r][1] + zrow[16 + tx];
            const float zo = acc[r][2] + zrow[32 + tx];
            const float zg_ = acc[r][3] + zrow[48 + tx];

            const int  dur  = fd[t * BB + b];
            const bool keep = (n > (dur >> 3));

            const float ig = 1.f / (1.f + expf(-zi));
            const float fg = 1.f / (1.f + expf(-zf));
            const float og = 1.f / (1.f + expf(-zo));
            const float gg = tanhf(zg_);

            float cn = fg * creg[r] + ig * gg;
            cn = keep ? creg[r] : cn;
            creg[r] = cn;
            const float hn = og * tanhf(cn);

            out[((size_t)(t * NN + n) * BB + b) * HH + j] = hn;
        }

        __syncthreads();   // all reads of Hs/ZXs done; all out-stores issued

        if (tid == 0) {
            __threadfence();                       // release
            atomicAdd(g_flags + t * NN + n, 1);    // arrive
        }
    }
}

// ---------------------------------------------------------------------------
extern "C" void kernel_launch(void* const* d_in, const int* in_sizes, int n_in,
                              void* d_out, int out_size)
{
    const float* x  = (const float*)d_in[0];   // [T,B,I] f32
    const int*   fd = (const int*)  d_in[1];   // [T,B]   i32
    const float* w  = (const float*)d_in[2];   // [N,I+H,4H] f32
    const float* bi = (const float*)d_in[3];   // [N,4H]
    const float* bh = (const float*)d_in[4];   // [N,4H]
    float* out = (float*)d_out;                // [T,N,B,H]

    dim3 zgrid(TT * BB / 64, FF / 64, NN);     // 256 x 16 x 8
    zx_kernel<<<zgrid, 256>>>(x, w, bi, bh);

    const int smem_bytes = (2 * 256 * 64 + 64 * 64) * sizeof(float);  // 144 KB
    cudaFuncSetAttribute(recur_kernel, cudaFuncAttributeMaxDynamicSharedMemorySize,
                         smem_bytes);
    recur_kernel<<<128, 256, smem_bytes>>>(w, fd, out);
}

// round 3
// speedup vs baseline: 1.6028x; 1.2361x over previous
#include <cuda_runtime.h>
#include <math.h>

#define TT 256
#define BB 64
#define II 256
#define HH 256
#define NN 8
#define FF 1024   // 4*H

// Scratch: precomputed x-path pre-activations ZX[t][n][b][f]  (512 MB)
__device__ float g_zx[(size_t)TT * NN * BB * FF];
// Per-(t,n) arrival flags for the persistent recurrence (zeroed by zx_kernel each run)
__device__ int g_flags[TT * NN];

// ---- packed fp32x2 helpers (Blackwell FFMA2) ----
__device__ __forceinline__ unsigned long long pk2(float a, float b) {
    unsigned long long r;
    asm("mov.b64 %0, {%1, %2};" : "=l"(r) : "f"(a), "f"(b));
    return r;
}
__device__ __forceinline__ unsigned long long f2fma(unsigned long long a,
                                                    unsigned long long b,
                                                    unsigned long long c) {
    unsigned long long d;
    asm("fma.rn.f32x2 %0, %1, %2, %3;" : "=l"(d) : "l"(a), "l"(b), "l"(c));
    return d;
}
__device__ __forceinline__ float2 unpk(unsigned long long v) {
    float2 r;
    asm("mov.b64 {%0, %1}, %2;" : "=f"(r.x), "=f"(r.y) : "l"(v));
    return r;
}

// ---------------------------------------------------------------------------
// Kernel 1: ZX[t,n,b,f] = sum_i x[t,b,i] * W[n,i,f] + bias_i[n,f] + bias_h[n,f]
// 64x64 tile, 256 threads, FFMA2 inner loop.
// Thread (tx,ty): rows m = mt*64 + 4*ty + r (r=0..3), cols f = ft*64 + 4*tx + g.
// ---------------------------------------------------------------------------
__global__ __launch_bounds__(256) void zx_kernel(
    const float* __restrict__ x,    // [T*B, I]
    const float* __restrict__ w,    // [N, I+H, FF]
    const float* __restrict__ bi,   // [N, FF]
    const float* __restrict__ bh)   // [N, FF]
{
    const int mt = blockIdx.x;
    const int ft = blockIdx.y;
    const int n  = blockIdx.z;
    const int tid = threadIdx.x;

    // zero the flags (T*N = 2048 = 8 CTAs x 256 threads)
    if (ft == 0 && n == 0 && mt < 8) g_flags[mt * 256 + tid] = 0;

    __shared__ float As[64 * 36];   // [m][k] row-major, stride 36 (pad: banks + 16B align)
    __shared__ float Bs[32 * 64];   // [k][c], c = local col = 4*tx + g

    const int tx = tid & 15;
    const int ty = tid >> 4;

    unsigned long long acc01[4], acc23[4];
    const unsigned long long z2 = pk2(0.f, 0.f);
#pragma unroll
    for (int r = 0; r < 4; r++) { acc01[r] = z2; acc23[r] = z2; }

    const float* wbase = w + (size_t)n * (II + HH) * FF + (size_t)ft * 64;

    // A-load mapping: k4 = tid&7 (float4 of k), m = tid>>3 (+32 second pass)
    const int ak4 = tid & 7;
    const int am  = tid >> 3;
    // B-load mapping: c = tid&63, k0 = tid>>6
    const int bc  = tid & 63;
    const int bk0 = tid >> 6;

    for (int kk = 0; kk < II; kk += 32) {
        // A tile: [64 m][32 k] row-major, coalesced float4 loads
#pragma unroll
        for (int p = 0; p < 2; p++) {
            const int m = am + 32 * p;
            const float4 v = *(const float4*)(x + (size_t)(mt * 64 + m) * II + kk + 4 * ak4);
            *(float4*)(As + m * 36 + 4 * ak4) = v;
        }
        // B tile: [32 k][64 c], c == f-local (identity), coalesced
#pragma unroll
        for (int p = 0; p < 8; p++) {
            const int k = bk0 + 4 * p;
            Bs[k * 64 + bc] = wbase[(size_t)(kk + k) * FF + bc];
        }
        __syncthreads();

#pragma unroll 8
        for (int k = 0; k < 32; k++) {
            const ulonglong2 bb = *(const ulonglong2*)(Bs + k * 64 + 4 * tx);
            const float a0 = As[(4 * ty + 0) * 36 + k];
            const float a1 = As[(4 * ty + 1) * 36 + k];
            const float a2 = As[(4 * ty + 2) * 36 + k];
            const float a3 = As[(4 * ty + 3) * 36 + k];
            unsigned long long ar;
            ar = pk2(a0, a0); acc01[0] = f2fma(ar, bb.x, acc01[0]); acc23[0] = f2fma(ar, bb.y, acc23[0]);
            ar = pk2(a1, a1); acc01[1] = f2fma(ar, bb.x, acc01[1]); acc23[1] = f2fma(ar, bb.y, acc23[1]);
            ar = pk2(a2, a2); acc01[2] = f2fma(ar, bb.x, acc01[2]); acc23[2] = f2fma(ar, bb.y, acc23[2]);
            ar = pk2(a3, a3); acc01[3] = f2fma(ar, bb.x, acc01[3]); acc23[3] = f2fma(ar, bb.y, acc23[3]);
        }
        __syncthreads();
    }

    // Epilogue: bias + contiguous float4 store
    const float4 bv1 = *(const float4*)(bi + (size_t)n * FF + ft * 64 + 4 * tx);
    const float4 bv2 = *(const float4*)(bh + (size_t)n * FF + ft * 64 + 4 * tx);
    const float4 bias = make_float4(bv1.x + bv2.x, bv1.y + bv2.y,
                                    bv1.z + bv2.z, bv1.w + bv2.w);
#pragma unroll
    for (int r = 0; r < 4; r++) {
        const int m = mt * 64 + 4 * ty + r;   // m = t*B + b
        const int t = m >> 6;
        const int b = m & 63;
        const float2 v01 = unpk(acc01[r]);
        const float2 v23 = unpk(acc23[r]);
        float4 o = make_float4(v01.x + bias.x, v01.y + bias.y,
                               v23.x + bias.z, v23.y + bias.w);
        *(float4*)(g_zx + ((size_t)(t * NN + n) * BB + b) * FF + ft * 64 + 4 * tx) = o;
    }
}

// ---------------------------------------------------------------------------
// Kernel 2: persistent recurrence. 128 CTAs (all co-resident), 256 threads.
// CTA (jt, n): h-columns [jt*16, jt*16+16) of branch n for all t.
// Ws[k][4*tx+g] = Wh[k][g*H + jt*16 + tx]  (one float4 = 4 gates of col j)
// Hs[k][b] ; thread rows b = 4*ty + r  (one broadcast float4 = 4 a-values)
// Inner loop per k: 2 LDS.128 + 4 MOV64 + 8 FFMA2.
// ---------------------------------------------------------------------------
__global__ __launch_bounds__(256, 1) void recur_kernel(
    const float* __restrict__ w,    // [N, I+H, FF]
    const int*   __restrict__ fd,   // [T*B]
    float* out)                     // [T, N, B, H]
{
    extern __shared__ float smem[];
    float* Ws  = smem;                  // [256][64]  64 KB
    float* Hs  = smem + 256 * 64;       // [256][64]  64 KB
    float* ZXs = smem + 2 * 256 * 64;   // [64][64]   16 KB

    const int jt = blockIdx.x & 15;
    const int n  = blockIdx.x >> 4;
    const int tid = threadIdx.x;
    const int tx = tid & 15;
    const int ty = tid >> 4;

    // ---- load Wh slice into SMEM once: Ws[k][4*txc+g] = Wh[k][g*H + jt*16 + txc]
    const float* wbase = w + (size_t)n * (II + HH) * FF + (size_t)II * FF;
    for (int i = tid; i < 256 * 64; i += 256) {
        const int k = i >> 6, c = i & 63;
        Ws[i] = wbase[(size_t)k * FF + (c & 3) * HH + jt * 16 + (c >> 2)];
    }

    // zx prefetch mapping: thread -> (b = tid>>2, g = tid&3), copies 16 floats
    const int zb = tid >> 2;
    const int zg = tid & 3;
    const unsigned zxs_dst = (unsigned)__cvta_generic_to_shared(ZXs + zb * 64 + zg * 16);

    // h load mapping: thread -> row b_ld, k-chunk kc (64 k each)
    const int b_ld = tid & 63;
    const int kc   = tid >> 6;

    // cell state registers: rows b = 4*ty + r; column j = jt*16 + tx
    float creg[4] = {0.f, 0.f, 0.f, 0.f};
    const int j = jt * 16 + tx;
    const unsigned long long z2 = pk2(0.f, 0.f);

    for (int t = 0; t < TT; t++) {
        // -- issue ZX prefetch for this step (overlaps the spin below) --
        {
            const float* zsrc = g_zx + ((size_t)(t * NN + n) * BB + zb) * FF
                                + zg * HH + jt * 16;
#pragma unroll
            for (int q = 0; q < 4; q++) {
                asm volatile("cp.async.ca.shared.global [%0], [%1], 16;\n"
                             :: "r"(zxs_dst + q * 16), "l"(zsrc + q * 4));
            }
            asm volatile("cp.async.commit_group;\n");
        }

        if (t > 0) {
            // -- wait for all 16 CTAs of branch n to publish h(t-1) --
            if (tid == 0) {
                int v;
                do {
                    asm volatile("ld.acquire.gpu.global.s32 %0, [%1];"
                                 : "=r"(v) : "l"(g_flags + (t - 1) * NN + n));
                } while (v < 16);
            }
            __syncthreads();   // propagate acquire to whole CTA

            // -- load h(t-1) tile [64 b][256 k] -> Hs[k][b] --
            const float* hrow = out + ((size_t)((t - 1) * NN + n) * BB + b_ld) * HH
                                + kc * 64;
#pragma unroll
            for (int i = 0; i < 16; i++) {
                const float4 v = *(const float4*)(hrow + i * 4);
                const int k = kc * 64 + i * 4;
                Hs[(k + 0) * 64 + b_ld] = v.x;
                Hs[(k + 1) * 64 + b_ld] = v.y;
                Hs[(k + 2) * 64 + b_ld] = v.z;
                Hs[(k + 3) * 64 + b_ld] = v.w;
            }
        }

        asm volatile("cp.async.wait_group 0;\n");
        __syncthreads();

        // -- GEMM: acc[r][g] = sum_k h[b=4ty+r][k] * Wh[k][g*H + j] --
        unsigned long long acc01[4], acc23[4];
#pragma unroll
        for (int r = 0; r < 4; r++) { acc01[r] = z2; acc23[r] = z2; }

        if (t > 0) {
#pragma unroll 8
            for (int k = 0; k < 256; k++) {
                const float4 av = *(const float4*)(Hs + k * 64 + 4 * ty);
                const ulonglong2 bb = *(const ulonglong2*)(Ws + k * 64 + 4 * tx);
                unsigned long long ar;
                ar = pk2(av.x, av.x); acc01[0] = f2fma(ar, bb.x, acc01[0]); acc23[0] = f2fma(ar, bb.y, acc23[0]);
                ar = pk2(av.y, av.y); acc01[1] = f2fma(ar, bb.x, acc01[1]); acc23[1] = f2fma(ar, bb.y, acc23[1]);
                ar = pk2(av.z, av.z); acc01[2] = f2fma(ar, bb.x, acc01[2]); acc23[2] = f2fma(ar, bb.y, acc23[2]);
                ar = pk2(av.w, av.w); acc01[3] = f2fma(ar, bb.x, acc01[3]); acc23[3] = f2fma(ar, bb.y, acc23[3]);
            }
        }

        // -- LSTM epilogue (thread-local) --
        const int4 dur4 = *(const int4*)(fd + t * BB + 4 * ty);
        const int durs[4] = {dur4.x, dur4.y, dur4.z, dur4.w};
#pragma unroll
        for (int r = 0; r < 4; r++) {
            const int b = 4 * ty + r;
            const float* zrow = ZXs + b * 64;
            const float2 a01 = unpk(acc01[r]);
            const float2 a23 = unpk(acc23[r]);
            const float zi = a01.x + zrow[tx];
            const float zf = a01.y + zrow[16 + tx];
            const float zo = a23.x + zrow[32 + tx];
            const float zg_ = a23.y + zrow[48 + tx];

            const bool keep = (n > (durs[r] >> 3));

            const float ig = 1.f / (1.f + expf(-zi));
            const float fg = 1.f / (1.f + expf(-zf));
            const float og = 1.f / (1.f + expf(-zo));
            const float gg = tanhf(zg_);

            float cn = fg * creg[r] + ig * gg;
            cn = keep ? creg[r] : cn;
            creg[r] = cn;
            const float hn = og * tanhf(cn);

            out[((size_t)(t * NN + n) * BB + b) * HH + j] = hn;
        }

        __syncthreads();   // all reads of Hs/ZXs done; all out-stores issued

        if (tid == 0) {
            __threadfence();                       // release
            atomicAdd(g_flags + t * NN + n, 1);    // arrive
        }
    }
}

// ---------------------------------------------------------------------------
extern "C" void kernel_launch(void* const* d_in, const int* in_sizes, int n_in,
                              void* d_out, int out_size)
{
    const float* x  = (const float*)d_in[0];   // [T,B,I] f32
    const int*   fd = (const int*)  d_in[1];   // [T,B]   i32
    const float* w  = (const float*)d_in[2];   // [N,I+H,4H] f32
    const float* bi = (const float*)d_in[3];   // [N,4H]
    const float* bh = (const float*)d_in[4];   // [N,4H]
    float* out = (float*)d_out;                // [T,N,B,H]

    dim3 zgrid(TT * BB / 64, FF / 64, NN);     // 256 x 16 x 8
    zx_kernel<<<zgrid, 256>>>(x, w, bi, bh);

    const int smem_bytes = (2 * 256 * 64 + 64 * 64) * sizeof(float);  // 144 KB
    cudaFuncSetAttribute(recur_kernel, cudaFuncAttributeMaxDynamicSharedMemorySize,
                         smem_bytes);
    recur_kernel<<<128, 256, smem_bytes>>>(w, fd, out);
}

// round 6
// speedup vs baseline: 2.0268x; 1.2645x over previous
#include <cuda_runtime.h>
#include <cuda_bf16.h>
#include <math.h>
#include <stdint.h>

#define TT 256
#define BB 64
#define II 256
#define HH 256
#define NN 8
#define FF 1024   // 4*H

// ---------------- scratch (device globals; no allocs) ----------------
__device__ float g_zx[(size_t)TT * NN * BB * FF];        // [t][n][b][f]  512 MB
__device__ int   g_flags[TT * NN];
__device__ __nv_bfloat16 g_xh[(size_t)TT * BB * II];     // X hi  [m][k]
__device__ __nv_bfloat16 g_xl[(size_t)TT * BB * II];     // X lo
__device__ __nv_bfloat16 g_wth[(size_t)NN * FF * II];    // W^T hi [n][f][k]
__device__ __nv_bfloat16 g_wtl[(size_t)NN * FF * II];    // W^T lo

// single dynamic-smem symbol, shared by all kernels
extern __shared__ char dynsmem[];

// ---------------- helpers ----------------
__device__ __forceinline__ uint32_t smem_u32(const void* p) {
    uint32_t a;
    asm("{ .reg .u64 t; cvta.to.shared.u64 t, %1; cvt.u32.u64 %0, t; }" : "=r"(a) : "l"(p));
    return a;
}

__device__ __forceinline__ void ldsm_x4(uint32_t* r, uint32_t addr) {
    asm volatile("ldmatrix.sync.aligned.m8n8.x4.shared.b16 {%0,%1,%2,%3}, [%4];"
                 : "=r"(r[0]), "=r"(r[1]), "=r"(r[2]), "=r"(r[3]) : "r"(addr));
}

__device__ __forceinline__ void mma_bf16(float* c, const uint32_t* a,
                                         uint32_t b0, uint32_t b1) {
    asm volatile(
        "mma.sync.aligned.m16n8k16.row.col.f32.bf16.bf16.f32 "
        "{%0,%1,%2,%3}, {%4,%5,%6,%7}, {%8,%9}, {%0,%1,%2,%3};"
        : "+f"(c[0]), "+f"(c[1]), "+f"(c[2]), "+f"(c[3])
        : "r"(a[0]), "r"(a[1]), "r"(a[2]), "r"(a[3]), "r"(b0), "r"(b1));
}

// ---- packed fp32x2 (FFMA2) ----
__device__ __forceinline__ unsigned long long pk2(float a, float b) {
    unsigned long long r; asm("mov.b64 %0, {%1, %2};" : "=l"(r) : "f"(a), "f"(b)); return r;
}
__device__ __forceinline__ unsigned long long f2fma(unsigned long long a, unsigned long long b,
                                                    unsigned long long c) {
    unsigned long long d; asm("fma.rn.f32x2 %0, %1, %2, %3;" : "=l"(d) : "l"(a), "l"(b), "l"(c)); return d;
}
__device__ __forceinline__ float2 unpk(unsigned long long v) {
    float2 r; asm("mov.b64 {%0, %1}, %2;" : "=f"(r.x), "=f"(r.y) : "l"(v)); return r;
}

// ---------------------------------------------------------------------------
// conv_x: split X into bf16 hi/lo. Also zeroes g_flags.
// ---------------------------------------------------------------------------
__global__ __launch_bounds__(256) void conv_x(const float* __restrict__ x) {
    if (blockIdx.x < 8) g_flags[blockIdx.x * 256 + threadIdx.x] = 0;
    const size_t i0 = ((size_t)blockIdx.x * 256 + threadIdx.x) * 4;
    const float4 v = *(const float4*)(x + i0);
    const float f[4] = {v.x, v.y, v.z, v.w};
    __nv_bfloat16 hv[4], lv[4];
#pragma unroll
    for (int j = 0; j < 4; j++) {
        hv[j] = __float2bfloat16(f[j]);
        lv[j] = __float2bfloat16(f[j] - __bfloat162float(hv[j]));
    }
    *reinterpret_cast<uint2*>(g_xh + i0) = *reinterpret_cast<uint2*>(hv);
    *reinterpret_cast<uint2*>(g_xl + i0) = *reinterpret_cast<uint2*>(lv);
}

// ---------------------------------------------------------------------------
// conv_w: transpose + split input-half weights: W[n][k<256][f] -> Wt[n][f][k]
// grid (32, 8, 8), block (32, 8)
// ---------------------------------------------------------------------------
__global__ void conv_w(const float* __restrict__ w) {
    __shared__ float tile[32][33];
    const int n = blockIdx.z, f0 = blockIdx.x * 32, k0 = blockIdx.y * 32;
    const int tx = threadIdx.x, ty = threadIdx.y;
#pragma unroll
    for (int j = 0; j < 4; j++)
        tile[ty + 8 * j][tx] = w[((size_t)n * (II + HH) + k0 + ty + 8 * j) * FF + f0 + tx];
    __syncthreads();
#pragma unroll
    for (int j = 0; j < 4; j++) {
        const int f = f0 + ty + 8 * j, k = k0 + tx;
        const float v = tile[tx][ty + 8 * j];
        const __nv_bfloat16 h = __float2bfloat16(v);
        const __nv_bfloat16 l = __float2bfloat16(v - __bfloat162float(h));
        const size_t idx = ((size_t)n * FF + f) * II + k;
        g_wth[idx] = h;
        g_wtl[idx] = l;
    }
}

// ---------------------------------------------------------------------------
// zx_hmma: ZX[t,n,b,f] = X @ W_in + bias, split-bf16 HMMA (mma.sync m16n8k16).
// grid (128 mt, 8 ft, 8 n), 256 threads = 8 warps (4 m x 2 f), warp = 32m x 64f.
// K slabs of 64, cp.async double-buffered, 12 slabs = 3 passes x 256 k.
// ---------------------------------------------------------------------------
#define ZA0    0
#define ZA1    18432
#define ZB0    36864
#define ZB1    55296
#define ZBIAS  73728
#define ZSMEM  74240
#define TSTRIDE 144     // bytes per smem row = 72 bf16 (64 data + 8 pad)

static __device__ __forceinline__ void zx_issue_slab(
    int s, int tid, int mt, int ft, int n, uint32_t sbase)
{
    const __nv_bfloat16* axs[3] = {g_xh, g_xh, g_xl};
    const __nv_bfloat16* bxs[3] = {g_wth, g_wtl, g_wth};
    const int pass = s >> 2, k0 = (s & 3) * 64, buf = s & 1;
    const __nv_bfloat16* A = axs[pass] + (size_t)mt * 128 * II + k0;
    const __nv_bfloat16* B = bxs[pass] + ((size_t)n * FF + ft * 128) * II + k0;
    const uint32_t ad = sbase + (buf ? ZA1 : ZA0);
    const uint32_t bd = sbase + (buf ? ZB1 : ZB0);
#pragma unroll
    for (int i = 0; i < 4; i++) {           // A: 128 rows x 8 chunks of 16B
        const int id = tid + 256 * i, r = id >> 3, ch = id & 7;
        asm volatile("cp.async.ca.shared.global [%0], [%1], 16;\n"
                     :: "r"(ad + r * TSTRIDE + ch * 16),
                        "l"((const void*)(A + (size_t)r * II + ch * 8)));
    }
#pragma unroll
    for (int i = 0; i < 4; i++) {           // B: 128 f-rows x 8 chunks
        const int id = tid + 256 * i, r = id >> 3, ch = id & 7;
        asm volatile("cp.async.ca.shared.global [%0], [%1], 16;\n"
                     :: "r"(bd + r * TSTRIDE + ch * 16),
                        "l"((const void*)(B + (size_t)r * II + ch * 8)));
    }
    asm volatile("cp.async.commit_group;\n");
}

__global__ __launch_bounds__(256) void zx_hmma(
    const float* __restrict__ bi, const float* __restrict__ bh)
{
    const uint32_t sbase = smem_u32(dynsmem);
    const int tid = threadIdx.x, wid = tid >> 5, lane = tid & 31;
    const int mt = blockIdx.x, ft = blockIdx.y, n = blockIdx.z;

    const int mwarp = wid & 3, fwarp = wid >> 2;
    const int lrow = lane & 7, lgrp = lane >> 3;
    // ldmatrix row/col offsets (atom order matches mma fragment layout)
    const int a_m = mwarp * 32 + (lgrp & 1) * 8 + lrow;   // + mf*16
    const int a_k = (lgrp >> 1) * 8;                       // + kstep*16
    const int b_n = fwarp * 64 + (lgrp >> 1) * 8 + lrow;   // + nf4*16
    const int b_k = (lgrp & 1) * 8;

    // bias slice (128 floats)
    float* bias_s = (float*)(dynsmem + ZBIAS);
    if (tid < 128)
        bias_s[tid] = bi[(size_t)n * FF + ft * 128 + tid]
                    + bh[(size_t)n * FF + ft * 128 + tid];

    float acc[2][8][4];
#pragma unroll
    for (int mf = 0; mf < 2; mf++)
#pragma unroll
        for (int nf = 0; nf < 8; nf++)
#pragma unroll
            for (int q = 0; q < 4; q++) acc[mf][nf][q] = 0.f;

    zx_issue_slab(0, tid, mt, ft, n, sbase);
    zx_issue_slab(1, tid, mt, ft, n, sbase);

    for (int s = 0; s < 12; s++) {
        if (s < 11) asm volatile("cp.async.wait_group 1;\n" ::: "memory");
        else        asm volatile("cp.async.wait_group 0;\n" ::: "memory");
        __syncthreads();
        const uint32_t abase = sbase + ((s & 1) ? ZA1 : ZA0);
        const uint32_t bbase = sbase + ((s & 1) ? ZB1 : ZB0);
#pragma unroll
        for (int ks = 0; ks < 4; ks++) {
            const int k0 = ks * 16;
            uint32_t a[2][4], b[4][4];
#pragma unroll
            for (int mf = 0; mf < 2; mf++)
                ldsm_x4(a[mf], abase + (a_m + mf * 16) * TSTRIDE + (k0 + a_k) * 2);
#pragma unroll
            for (int nf4 = 0; nf4 < 4; nf4++)
                ldsm_x4(b[nf4], bbase + (b_n + nf4 * 16) * TSTRIDE + (k0 + b_k) * 2);
#pragma unroll
            for (int mf = 0; mf < 2; mf++)
#pragma unroll
                for (int nf = 0; nf < 8; nf++)
                    mma_bf16(acc[mf][nf], a[mf], b[nf >> 1][(nf & 1) * 2],
                             b[nf >> 1][(nf & 1) * 2 + 1]);
        }
        __syncthreads();
        if (s + 2 < 12) zx_issue_slab(s + 2, tid, mt, ft, n, sbase);
    }

    // ---- epilogue: stage tile in smem (overlays slab buffers), then store ----
    __syncthreads();
    float* Zs = (float*)dynsmem;    // [128][132]
#pragma unroll
    for (int mf = 0; mf < 2; mf++)
#pragma unroll
        for (int nf = 0; nf < 8; nf++) {
            const int row = mwarp * 32 + mf * 16 + (lane >> 2);
            const int col = fwarp * 64 + nf * 8 + (lane & 3) * 2;
            *(float2*)(Zs + row * 132 + col) =
                make_float2(acc[mf][nf][0], acc[mf][nf][1]);
            *(float2*)(Zs + (row + 8) * 132 + col) =
                make_float2(acc[mf][nf][2], acc[mf][nf][3]);
        }
    __syncthreads();

    for (int i = tid; i < 128 * 32; i += 256) {
        const int row = i >> 5, c4 = (i & 31) * 4;
        const int m = mt * 128 + row, t = m >> 6, b = m & 63;
        float4 v = *(float4*)(Zs + row * 132 + c4);
        v.x += bias_s[c4];     v.y += bias_s[c4 + 1];
        v.z += bias_s[c4 + 2]; v.w += bias_s[c4 + 3];
        *(float4*)(g_zx + ((size_t)(t * NN + n) * BB + b) * FF + ft * 128 + c4) = v;
    }
}

// ---------------------------------------------------------------------------
// recur_kernel: persistent recurrence (FFMA2), 128 CTAs, 256 threads.
// (proven round-3 version; ZX layout [t][n][b][f])
// ---------------------------------------------------------------------------
__global__ __launch_bounds__(256, 1) void recur_kernel(
    const float* __restrict__ w,    // [N, I+H, FF]
    const int*   __restrict__ fd,   // [T*B]
    float* out)                     // [T, N, B, H]
{
    float* smem = (float*)dynsmem;
    float* Ws  = smem;                  // [256][64]  64 KB
    float* Hs  = smem + 256 * 64;       // [256][64]  64 KB
    float* ZXs = smem + 2 * 256 * 64;   // [64][64]   16 KB

    const int jt = blockIdx.x & 15;
    const int n  = blockIdx.x >> 4;
    const int tid = threadIdx.x;
    const int tx = tid & 15;
    const int ty = tid >> 4;

    // Wh slice: Ws[k][4*txc+g] = Wh[k][g*H + jt*16 + txc]
    const float* wbase = w + (size_t)n * (II + HH) * FF + (size_t)II * FF;
    for (int i = tid; i < 256 * 64; i += 256) {
        const int k = i >> 6, c = i & 63;
        Ws[i] = wbase[(size_t)k * FF + (c & 3) * HH + jt * 16 + (c >> 2)];
    }

    // zx prefetch mapping: thread -> (b = tid>>2, g = tid&3), copies 16 floats
    const int zb = tid >> 2;
    const int zg = tid & 3;
    const unsigned zxs_dst = (unsigned)__cvta_generic_to_shared(ZXs + zb * 64 + zg * 16);

    // h load mapping
    const int b_ld = tid & 63;
    const int kc   = tid >> 6;

    float creg[4] = {0.f, 0.f, 0.f, 0.f};
    const int j = jt * 16 + tx;
    const unsigned long long z2 = pk2(0.f, 0.f);

    for (int t = 0; t < TT; t++) {
        // ZX prefetch (overlaps spin)
        {
            const float* zsrc = g_zx + ((size_t)(t * NN + n) * BB + zb) * FF
                                + zg * HH + jt * 16;
#pragma unroll
            for (int q = 0; q < 4; q++) {
                asm volatile("cp.async.ca.shared.global [%0], [%1], 16;\n"
                             :: "r"(zxs_dst + q * 16), "l"(zsrc + q * 4));
            }
            asm volatile("cp.async.commit_group;\n");
        }

        if (t > 0) {
            if (tid == 0) {
                int v;
                do {
                    asm volatile("ld.acquire.gpu.global.s32 %0, [%1];"
                                 : "=r"(v) : "l"(g_flags + (t - 1) * NN + n));
                } while (v < 16);
            }
            __syncthreads();

            const float* hrow = out + ((size_t)((t - 1) * NN + n) * BB + b_ld) * HH
                                + kc * 64;
#pragma unroll
            for (int i = 0; i < 16; i++) {
                const float4 v = *(const float4*)(hrow + i * 4);
                const int k = kc * 64 + i * 4;
                Hs[(k + 0) * 64 + b_ld] = v.x;
                Hs[(k + 1) * 64 + b_ld] = v.y;
                Hs[(k + 2) * 64 + b_ld] = v.z;
                Hs[(k + 3) * 64 + b_ld] = v.w;
            }
        }

        asm volatile("cp.async.wait_group 0;\n");
        __syncthreads();

        unsigned long long acc01[4], acc23[4];
#pragma unroll
        for (int r = 0; r < 4; r++) { acc01[r] = z2; acc23[r] = z2; }

        if (t > 0) {
#pragma unroll 8
            for (int k = 0; k < 256; k++) {
                const float4 av = *(const float4*)(Hs + k * 64 + 4 * ty);
                const ulonglong2 bb = *(const ulonglong2*)(Ws + k * 64 + 4 * tx);
                unsigned long long ar;
                ar = pk2(av.x, av.x); acc01[0] = f2fma(ar, bb.x, acc01[0]); acc23[0] = f2fma(ar, bb.y, acc23[0]);
                ar = pk2(av.y, av.y); acc01[1] = f2fma(ar, bb.x, acc01[1]); acc23[1] = f2fma(ar, bb.y, acc23[1]);
                ar = pk2(av.z, av.z); acc01[2] = f2fma(ar, bb.x, acc01[2]); acc23[2] = f2fma(ar, bb.y, acc23[2]);
                ar = pk2(av.w, av.w); acc01[3] = f2fma(ar, bb.x, acc01[3]); acc23[3] = f2fma(ar, bb.y, acc23[3]);
            }
        }

        const int4 dur4 = *(const int4*)(fd + t * BB + 4 * ty);
        const int durs[4] = {dur4.x, dur4.y, dur4.z, dur4.w};
#pragma unroll
        for (int r = 0; r < 4; r++) {
            const int b = 4 * ty + r;
            const float* zrow = ZXs + b * 64;
            const float2 a01 = unpk(acc01[r]);
            const float2 a23 = unpk(acc23[r]);
            const float zi  = a01.x + zrow[tx];
            const float zf_ = a01.y + zrow[16 + tx];
            const float zo  = a23.x + zrow[32 + tx];
            const float zg_ = a23.y + zrow[48 + tx];

            const bool keep = (n > (durs[r] >> 3));

            const float ig = 1.f / (1.f + expf(-zi));
            const float fg = 1.f / (1.f + expf(-zf_));
            const float og = 1.f / (1.f + expf(-zo));
            const float gg = tanhf(zg_);

            float cn = fg * creg[r] + ig * gg;
            cn = keep ? creg[r] : cn;
            creg[r] = cn;
            const float hn = og * tanhf(cn);

            out[((size_t)(t * NN + n) * BB + b) * HH + j] = hn;
        }

        __syncthreads();

        if (tid == 0) {
            __threadfence();
            atomicAdd(g_flags + t * NN + n, 1);
        }
    }
}

// ---------------------------------------------------------------------------
extern "C" void kernel_launch(void* const* d_in, const int* in_sizes, int n_in,
                              void* d_out, int out_size)
{
    const float* x  = (const float*)d_in[0];   // [T,B,I] f32
    const int*   fd = (const int*)  d_in[1];   // [T,B]   i32
    const float* w  = (const float*)d_in[2];   // [N,I+H,4H] f32
    const float* bi = (const float*)d_in[3];   // [N,4H]
    const float* bh = (const float*)d_in[4];   // [N,4H]
    float* out = (float*)d_out;                // [T,N,B,H]

    conv_x<<<4096, 256>>>(x);
    conv_w<<<dim3(32, 8, 8), dim3(32, 8)>>>(w);

    cudaFuncSetAttribute(zx_hmma, cudaFuncAttributeMaxDynamicSharedMemorySize, ZSMEM);
    zx_hmma<<<dim3(128, 8, 8), 256, ZSMEM>>>(bi, bh);

    const int recur_smem = (2 * 256 * 64 + 64 * 64) * sizeof(float);   // 147456
    cudaFuncSetAttribute(recur_kernel, cudaFuncAttributeMaxDynamicSharedMemorySize,
                         recur_smem);
    recur_kernel<<<128, 256, recur_smem>>>(w, fd, out);
}

// round 7
// speedup vs baseline: 3.5059x; 1.7298x over previous
#include <cuda_runtime.h>
#include <cuda_bf16.h>
#include <math.h>
#include <stdint.h>

#define TT 256
#define BB 64
#define II 256
#define HH 256
#define NN 8
#define FF 1024   // 4*H

// ---------------- scratch (device globals; no allocs) ----------------
__device__ float g_zx[(size_t)TT * NN * BB * FF];        // [t][n][b][f]  512 MB
__device__ int   g_flags[TT * NN];
__device__ __nv_bfloat16 g_xh[(size_t)TT * BB * II];     // X hi  [m][k]
__device__ __nv_bfloat16 g_xl[(size_t)TT * BB * II];     // X lo
__device__ __nv_bfloat16 g_wth[(size_t)NN * FF * II];    // W^T hi [n][f][k]
__device__ __nv_bfloat16 g_wtl[(size_t)NN * FF * II];    // W^T lo

// single dynamic-smem symbol, shared by all kernels
extern __shared__ char dynsmem[];

// ---------------- helpers ----------------
__device__ __forceinline__ uint32_t smem_u32(const void* p) {
    uint32_t a;
    asm("{ .reg .u64 t; cvta.to.shared.u64 t, %1; cvt.u32.u64 %0, t; }" : "=r"(a) : "l"(p));
    return a;
}

__device__ __forceinline__ void ldsm_x4(uint32_t* r, uint32_t addr) {
    asm volatile("ldmatrix.sync.aligned.m8n8.x4.shared.b16 {%0,%1,%2,%3}, [%4];"
                 : "=r"(r[0]), "=r"(r[1]), "=r"(r[2]), "=r"(r[3]) : "r"(addr));
}

__device__ __forceinline__ void mma_bf16(float* c, const uint32_t* a,
                                         uint32_t b0, uint32_t b1) {
    asm volatile(
        "mma.sync.aligned.m16n8k16.row.col.f32.bf16.bf16.f32 "
        "{%0,%1,%2,%3}, {%4,%5,%6,%7}, {%8,%9}, {%0,%1,%2,%3};"
        : "+f"(c[0]), "+f"(c[1]), "+f"(c[2]), "+f"(c[3])
        : "r"(a[0]), "r"(a[1]), "r"(a[2]), "r"(a[3]), "r"(b0), "r"(b1));
}

// ---------------------------------------------------------------------------
// conv_x: split X into bf16 hi/lo. Also zeroes g_flags.
// ---------------------------------------------------------------------------
__global__ __launch_bounds__(256) void conv_x(const float* __restrict__ x) {
    if (blockIdx.x < 8) g_flags[blockIdx.x * 256 + threadIdx.x] = 0;
    const size_t i0 = ((size_t)blockIdx.x * 256 + threadIdx.x) * 4;
    const float4 v = *(const float4*)(x + i0);
    const float f[4] = {v.x, v.y, v.z, v.w};
    __nv_bfloat16 hv[4], lv[4];
#pragma unroll
    for (int j = 0; j < 4; j++) {
        hv[j] = __float2bfloat16(f[j]);
        lv[j] = __float2bfloat16(f[j] - __bfloat162float(hv[j]));
    }
    *reinterpret_cast<uint2*>(g_xh + i0) = *reinterpret_cast<uint2*>(hv);
    *reinterpret_cast<uint2*>(g_xl + i0) = *reinterpret_cast<uint2*>(lv);
}

// ---------------------------------------------------------------------------
// conv_w: transpose + split input-half weights: W[n][k<256][f] -> Wt[n][f][k]
// ---------------------------------------------------------------------------
__global__ void conv_w(const float* __restrict__ w) {
    __shared__ float tile[32][33];
    const int n = blockIdx.z, f0 = blockIdx.x * 32, k0 = blockIdx.y * 32;
    const int tx = threadIdx.x, ty = threadIdx.y;
#pragma unroll
    for (int j = 0; j < 4; j++)
        tile[ty + 8 * j][tx] = w[((size_t)n * (II + HH) + k0 + ty + 8 * j) * FF + f0 + tx];
    __syncthreads();
#pragma unroll
    for (int j = 0; j < 4; j++) {
        const int f = f0 + ty + 8 * j, k = k0 + tx;
        const float v = tile[tx][ty + 8 * j];
        const __nv_bfloat16 h = __float2bfloat16(v);
        const __nv_bfloat16 l = __float2bfloat16(v - __bfloat162float(h));
        const size_t idx = ((size_t)n * FF + f) * II + k;
        g_wth[idx] = h;
        g_wtl[idx] = l;
    }
}

// ---------------------------------------------------------------------------
// zx_hmma: ZX[t,n,b,f] = X @ W_in + bias, split-bf16 HMMA. (round-6, validated)
// ---------------------------------------------------------------------------
#define ZA0    0
#define ZA1    18432
#define ZB0    36864
#define ZB1    55296
#define ZBIAS  73728
#define ZSMEM  74240
#define TSTRIDE 144     // bytes per smem row = 72 bf16 (64 data + 8 pad)

static __device__ __forceinline__ void zx_issue_slab(
    int s, int tid, int mt, int ft, int n, uint32_t sbase)
{
    const __nv_bfloat16* axs[3] = {g_xh, g_xh, g_xl};
    const __nv_bfloat16* bxs[3] = {g_wth, g_wtl, g_wth};
    const int pass = s >> 2, k0 = (s & 3) * 64, buf = s & 1;
    const __nv_bfloat16* A = axs[pass] + (size_t)mt * 128 * II + k0;
    const __nv_bfloat16* B = bxs[pass] + ((size_t)n * FF + ft * 128) * II + k0;
    const uint32_t ad = sbase + (buf ? ZA1 : ZA0);
    const uint32_t bd = sbase + (buf ? ZB1 : ZB0);
#pragma unroll
    for (int i = 0; i < 4; i++) {
        const int id = tid + 256 * i, r = id >> 3, ch = id & 7;
        asm volatile("cp.async.ca.shared.global [%0], [%1], 16;\n"
                     :: "r"(ad + r * TSTRIDE + ch * 16),
                        "l"((const void*)(A + (size_t)r * II + ch * 8)));
    }
#pragma unroll
    for (int i = 0; i < 4; i++) {
        const int id = tid + 256 * i, r = id >> 3, ch = id & 7;
        asm volatile("cp.async.ca.shared.global [%0], [%1], 16;\n"
                     :: "r"(bd + r * TSTRIDE + ch * 16),
                        "l"((const void*)(B + (size_t)r * II + ch * 8)));
    }
    asm volatile("cp.async.commit_group;\n");
}

__global__ __launch_bounds__(256) void zx_hmma(
    const float* __restrict__ bi, const float* __restrict__ bh)
{
    const uint32_t sbase = smem_u32(dynsmem);
    const int tid = threadIdx.x, wid = tid >> 5, lane = tid & 31;
    const int mt = blockIdx.x, ft = blockIdx.y, n = blockIdx.z;

    const int mwarp = wid & 3, fwarp = wid >> 2;
    const int lrow = lane & 7, lgrp = lane >> 3;
    const int a_m = mwarp * 32 + (lgrp & 1) * 8 + lrow;
    const int a_k = (lgrp >> 1) * 8;
    const int b_n = fwarp * 64 + (lgrp >> 1) * 8 + lrow;
    const int b_k = (lgrp & 1) * 8;

    float* bias_s = (float*)(dynsmem + ZBIAS);
    if (tid < 128)
        bias_s[tid] = bi[(size_t)n * FF + ft * 128 + tid]
                    + bh[(size_t)n * FF + ft * 128 + tid];

    float acc[2][8][4];
#pragma unroll
    for (int mf = 0; mf < 2; mf++)
#pragma unroll
        for (int nf = 0; nf < 8; nf++)
#pragma unroll
            for (int q = 0; q < 4; q++) acc[mf][nf][q] = 0.f;

    zx_issue_slab(0, tid, mt, ft, n, sbase);
    zx_issue_slab(1, tid, mt, ft, n, sbase);

    for (int s = 0; s < 12; s++) {
        if (s < 11) asm volatile("cp.async.wait_group 1;\n" ::: "memory");
        else        asm volatile("cp.async.wait_group 0;\n" ::: "memory");
        __syncthreads();
        const uint32_t abase = sbase + ((s & 1) ? ZA1 : ZA0);
        const uint32_t bbase = sbase + ((s & 1) ? ZB1 : ZB0);
#pragma unroll
        for (int ks = 0; ks < 4; ks++) {
            const int k0 = ks * 16;
            uint32_t a[2][4], b[4][4];
#pragma unroll
            for (int mf = 0; mf < 2; mf++)
                ldsm_x4(a[mf], abase + (a_m + mf * 16) * TSTRIDE + (k0 + a_k) * 2);
#pragma unroll
            for (int nf4 = 0; nf4 < 4; nf4++)
                ldsm_x4(b[nf4], bbase + (b_n + nf4 * 16) * TSTRIDE + (k0 + b_k) * 2);
#pragma unroll
            for (int mf = 0; mf < 2; mf++)
#pragma unroll
                for (int nf = 0; nf < 8; nf++)
                    mma_bf16(acc[mf][nf], a[mf], b[nf >> 1][(nf & 1) * 2],
                             b[nf >> 1][(nf & 1) * 2 + 1]);
        }
        __syncthreads();
        if (s + 2 < 12) zx_issue_slab(s + 2, tid, mt, ft, n, sbase);
    }

    __syncthreads();
    float* Zs = (float*)dynsmem;    // [128][132]
#pragma unroll
    for (int mf = 0; mf < 2; mf++)
#pragma unroll
        for (int nf = 0; nf < 8; nf++) {
            const int row = mwarp * 32 + mf * 16 + (lane >> 2);
            const int col = fwarp * 64 + nf * 8 + (lane & 3) * 2;
            *(float2*)(Zs + row * 132 + col) =
                make_float2(acc[mf][nf][0], acc[mf][nf][1]);
            *(float2*)(Zs + (row + 8) * 132 + col) =
                make_float2(acc[mf][nf][2], acc[mf][nf][3]);
        }
    __syncthreads();

    for (int i = tid; i < 128 * 32; i += 256) {
        const int row = i >> 5, c4 = (i & 31) * 4;
        const int m = mt * 128 + row, t = m >> 6, b = m & 63;
        float4 v = *(float4*)(Zs + row * 132 + c4);
        v.x += bias_s[c4];     v.y += bias_s[c4 + 1];
        v.z += bias_s[c4 + 2]; v.w += bias_s[c4 + 3];
        *(float4*)(g_zx + ((size_t)(t * NN + n) * BB + b) * FF + ft * 128 + c4) = v;
    }
}

// ---------------------------------------------------------------------------
// recur_kernel: persistent recurrence, split-bf16 HMMA. 128 CTAs, 256 threads.
// SMEM: Whh/Whl [c=64][k=256+8] bf16 (B operand, K-major), Hh/Hl [b=64][k+8]
// bf16 (A operand), ZXs [b][64] f32 (x-path preact), Zs [b][68] f32 (h-path z).
// c ordering: c = 4*hl + gate  ->  f = gate*H + jt*16 + hl.
// ---------------------------------------------------------------------------
#define WSTR   264                  // bf16 elems per smem row (256 + 8 pad)
#define R_WHH  0
#define R_WHL  33792
#define R_HH   67584
#define R_HL   101376
#define R_ZXS  135168
#define R_ZS   151552
#define R_SMEM 168960

__global__ __launch_bounds__(256, 1) void recur_kernel(
    const float* __restrict__ w,    // [N, I+H, FF]
    const int*   __restrict__ fd,   // [T*B]
    float* out)                     // [T, N, B, H]
{
    char* sm = dynsmem;
    const uint32_t sbase = smem_u32(sm);
    __nv_bfloat16* Whh = (__nv_bfloat16*)(sm + R_WHH);
    __nv_bfloat16* Whl = (__nv_bfloat16*)(sm + R_WHL);
    __nv_bfloat16* Hh  = (__nv_bfloat16*)(sm + R_HH);
    __nv_bfloat16* Hl  = (__nv_bfloat16*)(sm + R_HL);
    float* ZXs = (float*)(sm + R_ZXS);   // [64][64]
    float* Zs  = (float*)(sm + R_ZS);    // [64][68]

    const int jt = blockIdx.x & 15;
    const int n  = blockIdx.x >> 4;
    const int tid = threadIdx.x;
    const int wid = tid >> 5, lane = tid & 31;
    const int tx = tid & 15;
    const int ty = tid >> 4;

    // warp tiling: mw = b-half (32), nw = c-quarter (16)
    const int mw = wid & 1, nw = wid >> 1;
    const int lrow = lane & 7, lgrp = lane >> 3;
    const int a_row = mw * 32 + (lgrp & 1) * 8 + lrow;   // + ma*16
    const int a_kof = (lgrp >> 1) * 8;
    const int b_row = nw * 16 + (lgrp >> 1) * 8 + lrow;
    const int b_kof = (lgrp & 1) * 8;

    // ---- convert Wh slice to bf16 hi/lo, K-major [c][k] ----
    const float* wbase = w + (size_t)n * (II + HH) * FF + (size_t)II * FF;
    for (int i = tid; i < 64 * 256; i += 256) {
        const int k = i >> 6, q = i & 63;
        const int g = q >> 4, hl = q & 15;
        const float v = wbase[(size_t)k * FF + g * HH + jt * 16 + hl];
        const int c = 4 * hl + g;
        const __nv_bfloat16 h = __float2bfloat16(v);
        Whh[c * WSTR + k] = h;
        Whl[c * WSTR + k] = __float2bfloat16(v - __bfloat162float(h));
    }

    // zx prefetch mapping (ZXs[b][g*16 + hl])
    const int zb = tid >> 2;
    const int zg = tid & 3;
    const uint32_t zxs_dst = sbase + R_ZXS + (zb * 64 + zg * 16) * 4;

    // h convert mapping: lane -> k (coalesced), few b rows per thread
    const int hk4 = (tid & 63) * 4;
    const int hb0 = tid >> 6;

    float creg[4] = {0.f, 0.f, 0.f, 0.f};
    const int j = jt * 16 + tx;

    for (int t = 0; t < TT; t++) {
        // -- ZX prefetch for this step (overlaps the spin) --
        {
            const float* zsrc = g_zx + ((size_t)(t * NN + n) * BB + zb) * FF
                                + zg * HH + jt * 16;
#pragma unroll
            for (int q = 0; q < 4; q++) {
                asm volatile("cp.async.ca.shared.global [%0], [%1], 16;\n"
                             :: "r"(zxs_dst + q * 16), "l"(zsrc + q * 4));
            }
            asm volatile("cp.async.commit_group;\n");
        }

        if (t > 0) {
            if (tid == 0) {
                int v;
                do {
                    asm volatile("ld.acquire.gpu.global.s32 %0, [%1];"
                                 : "=r"(v) : "l"(g_flags + (t - 1) * NN + n));
                } while (v < 16);
            }
            __syncthreads();

            // -- load h(t-1), split to bf16 hi/lo in SMEM (A row-major) --
            const float* hbase = out + ((size_t)((t - 1) * NN + n) * BB) * HH + hk4;
#pragma unroll
            for (int i = 0; i < 16; i++) {
                const int b = hb0 + 4 * i;
                const float4 v = *(const float4*)(hbase + (size_t)b * HH);
                const float f[4] = {v.x, v.y, v.z, v.w};
                __nv_bfloat16 hv[4], lv[4];
#pragma unroll
                for (int q = 0; q < 4; q++) {
                    hv[q] = __float2bfloat16(f[q]);
                    lv[q] = __float2bfloat16(f[q] - __bfloat162float(hv[q]));
                }
                *(uint2*)(Hh + b * WSTR + hk4) = *(uint2*)hv;
                *(uint2*)(Hl + b * WSTR + hk4) = *(uint2*)lv;
            }
        }

        asm volatile("cp.async.wait_group 0;\n" ::: "memory");
        __syncthreads();

        // -- HMMA GEMM: z_h[b][c] = h @ Wh (3-product split-bf16) --
        float acc[2][2][4];
#pragma unroll
        for (int ma = 0; ma < 2; ma++)
#pragma unroll
            for (int nf = 0; nf < 2; nf++)
#pragma unroll
                for (int q = 0; q < 4; q++) acc[ma][nf][q] = 0.f;

        if (t > 0) {
#pragma unroll 4
            for (int ks = 0; ks < 16; ks++) {
                const int k0 = ks * 16;
                uint32_t ah[2][4], al[2][4], bh[4], bl[4];
#pragma unroll
                for (int ma = 0; ma < 2; ma++) {
                    ldsm_x4(ah[ma], sbase + R_HH + ((a_row + ma * 16) * WSTR + k0 + a_kof) * 2);
                    ldsm_x4(al[ma], sbase + R_HL + ((a_row + ma * 16) * WSTR + k0 + a_kof) * 2);
                }
                ldsm_x4(bh, sbase + R_WHH + (b_row * WSTR + k0 + b_kof) * 2);
                ldsm_x4(bl, sbase + R_WHL + (b_row * WSTR + k0 + b_kof) * 2);
#pragma unroll
                for (int ma = 0; ma < 2; ma++)
#pragma unroll
                    for (int nf = 0; nf < 2; nf++) {
                        mma_bf16(acc[ma][nf], ah[ma], bh[nf * 2], bh[nf * 2 + 1]);
                        mma_bf16(acc[ma][nf], ah[ma], bl[nf * 2], bl[nf * 2 + 1]);
                        mma_bf16(acc[ma][nf], al[ma], bh[nf * 2], bh[nf * 2 + 1]);
                    }
            }
        }

        // -- stage z_h fragments into Zs[b][c] --
#pragma unroll
        for (int ma = 0; ma < 2; ma++)
#pragma unroll
            for (int nf = 0; nf < 2; nf++) {
                const int row = mw * 32 + ma * 16 + (lane >> 2);
                const int col = nw * 16 + nf * 8 + (lane & 3) * 2;
                *(float2*)(Zs + row * 68 + col) =
                    make_float2(acc[ma][nf][0], acc[ma][nf][1]);
                *(float2*)(Zs + (row + 8) * 68 + col) =
                    make_float2(acc[ma][nf][2], acc[ma][nf][3]);
            }
        __syncthreads();

        // -- LSTM epilogue: z = Zs (h-path) + ZXs (x-path) --
        const int4 dur4 = *(const int4*)(fd + t * BB + 4 * ty);
        const int durs[4] = {dur4.x, dur4.y, dur4.z, dur4.w};
#pragma unroll
        for (int r = 0; r < 4; r++) {
            const int b = 4 * ty + r;
            const float4 zh = *(const float4*)(Zs + b * 68 + 4 * tx);  // i,f,o,g
            const float zi  = zh.x + ZXs[b * 64 + tx];
            const float zf_ = zh.y + ZXs[b * 64 + 16 + tx];
            const float zo  = zh.z + ZXs[b * 64 + 32 + tx];
            const float zg_ = zh.w + ZXs[b * 64 + 48 + tx];

            const bool keep = (n > (durs[r] >> 3));

            const float ig = 1.f / (1.f + expf(-zi));
            const float fg = 1.f / (1.f + expf(-zf_));
            const float og = 1.f / (1.f + expf(-zo));
            const float gg = tanhf(zg_);

            float cn = fg * creg[r] + ig * gg;
            cn = keep ? creg[r] : cn;
            creg[r] = cn;
            const float hn = og * tanhf(cn);

            out[((size_t)(t * NN + n) * BB + b) * HH + j] = hn;
        }

        __syncthreads();   // Zs/ZXs reads done; out stores issued

        if (tid == 0) {
            __threadfence();
            atomicAdd(g_flags + t * NN + n, 1);
        }
    }
}

// ---------------------------------------------------------------------------
extern "C" void kernel_launch(void* const* d_in, const int* in_sizes, int n_in,
                              void* d_out, int out_size)
{
    const float* x  = (const float*)d_in[0];   // [T,B,I] f32
    const int*   fd = (const int*)  d_in[1];   // [T,B]   i32
    const float* w  = (const float*)d_in[2];   // [N,I+H,4H] f32
    const float* bi = (const float*)d_in[3];   // [N,4H]
    const float* bh = (const float*)d_in[4];   // [N,4H]
    float* out = (float*)d_out;                // [T,N,B,H]

    conv_x<<<4096, 256>>>(x);
    conv_w<<<dim3(32, 8, 8), dim3(32, 8)>>>(w);

    cudaFuncSetAttribute(zx_hmma, cudaFuncAttributeMaxDynamicSharedMemorySize, ZSMEM);
    zx_hmma<<<dim3(128, 8, 8), 256, ZSMEM>>>(bi, bh);

    cudaFuncSetAttribute(recur_kernel, cudaFuncAttributeMaxDynamicSharedMemorySize,
                         R_SMEM);
    recur_kernel<<<128, 256, R_SMEM>>>(w, fd, out);
}

// round 8
// speedup vs baseline: 3.8318x; 1.0930x over previous
#include <cuda_runtime.h>
#include <cuda_bf16.h>
#include <math.h>
#include <stdint.h>

#define TT 256
#define BB 64
#define II 256
#define HH 256
#define NN 8
#define FF 1024   // 4*H

// ---------------- scratch (device globals; no allocs) ----------------
__device__ int   g_flags[TT * NN];
__device__ __nv_bfloat16 g_xh[(size_t)TT * BB * II];     // X hi  [m][k]
__device__ __nv_bfloat16 g_xl[(size_t)TT * BB * II];     // X lo
__device__ __nv_bfloat16 g_wth[(size_t)NN * FF * II];    // Wx^T hi [n][f][k]
__device__ __nv_bfloat16 g_wtl[(size_t)NN * FF * II];    // Wx^T lo

extern __shared__ char dynsmem[];

// ---------------- helpers ----------------
__device__ __forceinline__ uint32_t smem_u32(const void* p) {
    uint32_t a;
    asm("{ .reg .u64 t; cvta.to.shared.u64 t, %1; cvt.u32.u64 %0, t; }" : "=r"(a) : "l"(p));
    return a;
}

__device__ __forceinline__ void ldsm_x4(uint32_t* r, uint32_t addr) {
    asm volatile("ldmatrix.sync.aligned.m8n8.x4.shared.b16 {%0,%1,%2,%3}, [%4];"
                 : "=r"(r[0]), "=r"(r[1]), "=r"(r[2]), "=r"(r[3]) : "r"(addr));
}

__device__ __forceinline__ void mma_bf16(float* c, const uint32_t* a,
                                         uint32_t b0, uint32_t b1) {
    asm volatile(
        "mma.sync.aligned.m16n8k16.row.col.f32.bf16.bf16.f32 "
        "{%0,%1,%2,%3}, {%4,%5,%6,%7}, {%8,%9}, {%0,%1,%2,%3};"
        : "+f"(c[0]), "+f"(c[1]), "+f"(c[2]), "+f"(c[3])
        : "r"(a[0]), "r"(a[1]), "r"(a[2]), "r"(a[3]), "r"(b0), "r"(b1));
}

// ---------------------------------------------------------------------------
// conv_x: split X into bf16 hi/lo. Also zeroes g_flags.
// ---------------------------------------------------------------------------
__global__ __launch_bounds__(256) void conv_x(const float* __restrict__ x) {
    if (blockIdx.x < 8) g_flags[blockIdx.x * 256 + threadIdx.x] = 0;
    const size_t i0 = ((size_t)blockIdx.x * 256 + threadIdx.x) * 4;
    const float4 v = *(const float4*)(x + i0);
    const float f[4] = {v.x, v.y, v.z, v.w};
    __nv_bfloat16 hv[4], lv[4];
#pragma unroll
    for (int j = 0; j < 4; j++) {
        hv[j] = __float2bfloat16(f[j]);
        lv[j] = __float2bfloat16(f[j] - __bfloat162float(hv[j]));
    }
    *reinterpret_cast<uint2*>(g_xh + i0) = *reinterpret_cast<uint2*>(hv);
    *reinterpret_cast<uint2*>(g_xl + i0) = *reinterpret_cast<uint2*>(lv);
}

// ---------------------------------------------------------------------------
// conv_w: transpose + split input-half weights: W[n][k<256][f] -> Wt[n][f][k]
// ---------------------------------------------------------------------------
__global__ void conv_w(const float* __restrict__ w) {
    __shared__ float tile[32][33];
    const int n = blockIdx.z, f0 = blockIdx.x * 32, k0 = blockIdx.y * 32;
    const int tx = threadIdx.x, ty = threadIdx.y;
#pragma unroll
    for (int j = 0; j < 4; j++)
        tile[ty + 8 * j][tx] = w[((size_t)n * (II + HH) + k0 + ty + 8 * j) * FF + f0 + tx];
    __syncthreads();
#pragma unroll
    for (int j = 0; j < 4; j++) {
        const int f = f0 + ty + 8 * j, k = k0 + tx;
        const float v = tile[tx][ty + 8 * j];
        const __nv_bfloat16 h = __float2bfloat16(v);
        const __nv_bfloat16 l = __float2bfloat16(v - __bfloat162float(h));
        const size_t idx = ((size_t)n * FF + f) * II + k;
        g_wth[idx] = h;
        g_wtl[idx] = l;
    }
}

// ---------------------------------------------------------------------------
// recur_kernel: fully fused persistent LSTM. 128 CTAs (jt, n), 256 threads.
// Per step: z = X(t) @ Wx + h(t-1) @ Wh + bias, all via split-bf16 HMMA with
// fp32 fragment accumulation, then gate/cell/mask epilogue.
// SMEM: Wx hi/lo + Wh hi/lo [c=64][k=256] K-major (B operands, resident),
//       one A-tile buffer [64][256] hi/lo (holds X, then H within a step),
//       Zs [64][68] f32 staging.
// c ordering: c = 4*hl + gate  ->  f = gate*H + jt*16 + hl.
// ---------------------------------------------------------------------------
#define WSTR   264                  // bf16 elems per smem row (256 + 8 pad)
#define S_WXH  0
#define S_WXL  33792
#define S_WHH  67584
#define S_WHL  101376
#define S_AH   135168
#define S_AL   168960
#define S_ZS   202752               // 64*68*4 = 17408
#define S_TOT  220160

__device__ __forceinline__ void gemm3_acc(
    float acc[2][2][4], uint32_t sbase,
    uint32_t bH, uint32_t bL,
    int a_row, int a_kof, int b_row, int b_kof)
{
#pragma unroll 4
    for (int ks = 0; ks < 16; ks++) {
        const int k0 = ks * 16;
        uint32_t ah[2][4], al[2][4], bh[4], bl[4];
#pragma unroll
        for (int ma = 0; ma < 2; ma++) {
            ldsm_x4(ah[ma], sbase + S_AH + ((a_row + ma * 16) * WSTR + k0 + a_kof) * 2);
            ldsm_x4(al[ma], sbase + S_AL + ((a_row + ma * 16) * WSTR + k0 + a_kof) * 2);
        }
        ldsm_x4(bh, sbase + bH + (b_row * WSTR + k0 + b_kof) * 2);
        ldsm_x4(bl, sbase + bL + (b_row * WSTR + k0 + b_kof) * 2);
#pragma unroll
        for (int ma = 0; ma < 2; ma++)
#pragma unroll
            for (int nf = 0; nf < 2; nf++) {
                mma_bf16(acc[ma][nf], ah[ma], bh[nf * 2], bh[nf * 2 + 1]);
                mma_bf16(acc[ma][nf], ah[ma], bl[nf * 2], bl[nf * 2 + 1]);
                mma_bf16(acc[ma][nf], al[ma], bh[nf * 2], bh[nf * 2 + 1]);
            }
    }
}

__global__ __launch_bounds__(256, 1) void recur_kernel(
    const float* __restrict__ w,    // [N, I+H, FF]
    const float* __restrict__ bi,   // [N, FF]
    const float* __restrict__ bh_,  // [N, FF]
    const int*   __restrict__ fd,   // [T*B]
    float* out)                     // [T, N, B, H]
{
    char* sm = dynsmem;
    const uint32_t sbase = smem_u32(sm);
    __nv_bfloat16* Wxh = (__nv_bfloat16*)(sm + S_WXH);
    __nv_bfloat16* Wxl = (__nv_bfloat16*)(sm + S_WXL);
    __nv_bfloat16* Whh = (__nv_bfloat16*)(sm + S_WHH);
    __nv_bfloat16* Whl = (__nv_bfloat16*)(sm + S_WHL);
    __nv_bfloat16* Ah  = (__nv_bfloat16*)(sm + S_AH);
    __nv_bfloat16* Al  = (__nv_bfloat16*)(sm + S_AL);
    float* Zs = (float*)(sm + S_ZS);     // [64][68]

    const int jt = blockIdx.x & 15;
    const int n  = blockIdx.x >> 4;
    const int tid = threadIdx.x;
    const int wid = tid >> 5, lane = tid & 31;
    const int tx = tid & 15;
    const int ty = tid >> 4;

    // warp tiling: mw = b-half (32), nw = c-quarter (16)
    const int mw = wid & 1, nw = wid >> 1;
    const int lrow = lane & 7, lgrp = lane >> 3;
    const int a_row = mw * 32 + (lgrp & 1) * 8 + lrow;   // + ma*16
    const int a_kof = (lgrp >> 1) * 8;
    const int b_row = nw * 16 + (lgrp >> 1) * 8 + lrow;
    const int b_kof = (lgrp & 1) * 8;

    // ---- prologue: load Wx (bf16 from g_wt*) and convert Wh (fp32 split) ----
    for (int i = tid; i < 64 * 256; i += 256) {
        const int c = i >> 8, k = i & 255;
        const int g = c & 3, hl = c >> 2;
        const size_t src = ((size_t)n * FF + g * HH + jt * 16 + hl) * II + k;
        Wxh[c * WSTR + k] = g_wth[src];
        Wxl[c * WSTR + k] = g_wtl[src];
    }
    const float* wbase = w + (size_t)n * (II + HH) * FF + (size_t)II * FF;
    for (int i = tid; i < 64 * 256; i += 256) {
        const int k = i >> 6, q = i & 63;
        const int g = q >> 4, hl = q & 15;
        const float v = wbase[(size_t)k * FF + g * HH + jt * 16 + hl];
        const int c = 4 * hl + g;
        const __nv_bfloat16 h = __float2bfloat16(v);
        Whh[c * WSTR + k] = h;
        Whl[c * WSTR + k] = __float2bfloat16(v - __bfloat162float(h));
    }

    // bias registers: thread's column j, 4 gates
    const int j = jt * 16 + tx;
    float bias4[4];
#pragma unroll
    for (int g = 0; g < 4; g++)
        bias4[g] = bi[(size_t)n * FF + g * HH + j] + bh_[(size_t)n * FF + g * HH + j];

    // h load/convert mapping (fp32 -> split bf16 into Ah/Al)
    const int hk4 = (tid & 63) * 4;
    const int hb0 = tid >> 6;

    float creg[4] = {0.f, 0.f, 0.f, 0.f};

    // ---- load X(0) tile and run its x-GEMM ----
    __syncthreads();   // weights visible
    {
#pragma unroll
        for (int i = 0; i < 8; i++) {
            const int id = tid + 256 * i, r = id >> 5, ch = id & 31;
            asm volatile("cp.async.ca.shared.global [%0], [%1], 16;\n"
                         :: "r"(sbase + S_AH + r * 528 + ch * 16),
                            "l"((const void*)(g_xh + (size_t)r * II + ch * 8)));
            asm volatile("cp.async.ca.shared.global [%0], [%1], 16;\n"
                         :: "r"(sbase + S_AL + r * 528 + ch * 16),
                            "l"((const void*)(g_xl + (size_t)r * II + ch * 8)));
        }
        asm volatile("cp.async.commit_group;\n");
        asm volatile("cp.async.wait_group 0;\n" ::: "memory");
    }
    __syncthreads();

    float acc[2][2][4];
#pragma unroll
    for (int ma = 0; ma < 2; ma++)
#pragma unroll
        for (int nf = 0; nf < 2; nf++)
#pragma unroll
            for (int q = 0; q < 4; q++) acc[ma][nf][q] = 0.f;
    gemm3_acc(acc, sbase, S_WXH, S_WXL, a_row, a_kof, b_row, b_kof);

    for (int t = 0; t < TT; t++) {
        if (t > 0) {
            // wait for all 16 CTAs of branch n to publish h(t-1)
            if (tid == 0) {
                int v;
                do {
                    asm volatile("ld.acquire.gpu.global.s32 %0, [%1];"
                                 : "=r"(v) : "l"(g_flags + (t - 1) * NN + n));
                } while (v < 16);
            }
            __syncthreads();   // also guards Ah/Al reuse (x-GEMM done in all warps)

            // load h(t-1), split to bf16 hi/lo into Ah/Al
            const float* hbase = out + ((size_t)((t - 1) * NN + n) * BB) * HH + hk4;
#pragma unroll
            for (int i = 0; i < 16; i++) {
                const int b = hb0 + 4 * i;
                const float4 v = *(const float4*)(hbase + (size_t)b * HH);
                const float f[4] = {v.x, v.y, v.z, v.w};
                __nv_bfloat16 hv[4], lv[4];
#pragma unroll
                for (int q = 0; q < 4; q++) {
                    hv[q] = __float2bfloat16(f[q]);
                    lv[q] = __float2bfloat16(f[q] - __bfloat162float(hv[q]));
                }
                *(uint2*)(Ah + b * WSTR + hk4) = *(uint2*)hv;
                *(uint2*)(Al + b * WSTR + hk4) = *(uint2*)lv;
            }
            __syncthreads();

            // h-GEMM accumulates on top of the x-part already in acc
            gemm3_acc(acc, sbase, S_WHH, S_WHL, a_row, a_kof, b_row, b_kof);
        }

        // -- stage z fragments into Zs[b][c] --
#pragma unroll
        for (int ma = 0; ma < 2; ma++)
#pragma unroll
            for (int nf = 0; nf < 2; nf++) {
                const int row = mw * 32 + ma * 16 + (lane >> 2);
                const int col = nw * 16 + nf * 8 + (lane & 3) * 2;
                *(float2*)(Zs + row * 68 + col) =
                    make_float2(acc[ma][nf][0], acc[ma][nf][1]);
                *(float2*)(Zs + (row + 8) * 68 + col) =
                    make_float2(acc[ma][nf][2], acc[ma][nf][3]);
            }
        __syncthreads();

        // -- prefetch X(t+1) (Ah/Al free; overlaps epilogue) --
        if (t + 1 < TT) {
            const __nv_bfloat16* xh = g_xh + (size_t)(t + 1) * BB * II;
            const __nv_bfloat16* xl = g_xl + (size_t)(t + 1) * BB * II;
#pragma unroll
            for (int i = 0; i < 8; i++) {
                const int id = tid + 256 * i, r = id >> 5, ch = id & 31;
                asm volatile("cp.async.ca.shared.global [%0], [%1], 16;\n"
                             :: "r"(sbase + S_AH + r * 528 + ch * 16),
                                "l"((const void*)(xh + (size_t)r * II + ch * 8)));
                asm volatile("cp.async.ca.shared.global [%0], [%1], 16;\n"
                             :: "r"(sbase + S_AL + r * 528 + ch * 16),
                                "l"((const void*)(xl + (size_t)r * II + ch * 8)));
            }
            asm volatile("cp.async.commit_group;\n");
        }

        // -- LSTM epilogue --
        const int4 dur4 = *(const int4*)(fd + t * BB + 4 * ty);
        const int durs[4] = {dur4.x, dur4.y, dur4.z, dur4.w};
#pragma unroll
        for (int r = 0; r < 4; r++) {
            const int b = 4 * ty + r;
            const float4 zh = *(const float4*)(Zs + b * 68 + 4 * tx);  // i,f,o,g
            const float zi  = zh.x + bias4[0];
            const float zf_ = zh.y + bias4[1];
            const float zo  = zh.z + bias4[2];
            const float zg_ = zh.w + bias4[3];

            const bool keep = (n > (durs[r] >> 3));

            const float ig = 1.f / (1.f + expf(-zi));
            const float fg = 1.f / (1.f + expf(-zf_));
            const float og = 1.f / (1.f + expf(-zo));
            const float gg = tanhf(zg_);

            float cn = fg * creg[r] + ig * gg;
            cn = keep ? creg[r] : cn;
            creg[r] = cn;
            const float hn = og * tanhf(cn);

            out[((size_t)(t * NN + n) * BB + b) * HH + j] = hn;
        }

        __syncthreads();   // Zs reads done; out stores issued

        if (tid == 0) {
            __threadfence();
            atomicAdd(g_flags + t * NN + n, 1);
        }

        // -- x-GEMM for step t+1 (hides in the publish->wait slack) --
        if (t + 1 < TT) {
            asm volatile("cp.async.wait_group 0;\n" ::: "memory");
            __syncthreads();
#pragma unroll
            for (int ma = 0; ma < 2; ma++)
#pragma unroll
                for (int nf = 0; nf < 2; nf++)
#pragma unroll
                    for (int q = 0; q < 4; q++) acc[ma][nf][q] = 0.f;
            gemm3_acc(acc, sbase, S_WXH, S_WXL, a_row, a_kof, b_row, b_kof);
        }
    }
}

// ---------------------------------------------------------------------------
extern "C" void kernel_launch(void* const* d_in, const int* in_sizes, int n_in,
                              void* d_out, int out_size)
{
    const float* x  = (const float*)d_in[0];   // [T,B,I] f32
    const int*   fd = (const int*)  d_in[1];   // [T,B]   i32
    const float* w  = (const float*)d_in[2];   // [N,I+H,4H] f32
    const float* bi = (const float*)d_in[3];   // [N,4H]
    const float* bh = (const float*)d_in[4];   // [N,4H]
    float* out = (float*)d_out;                // [T,N,B,H]

    conv_x<<<4096, 256>>>(x);
    conv_w<<<dim3(32, 8, 8), dim3(32, 8)>>>(w);

    cudaFuncSetAttribute(recur_kernel, cudaFuncAttributeMaxDynamicSharedMemorySize,
                         S_TOT);
    recur_kernel<<<128, 256, S_TOT>>>(w, bi, bh, fd, out);
}

// round 9
// speedup vs baseline: 4.2484x; 1.1087x over previous
#include <cuda_runtime.h>
#include <cuda_bf16.h>
#include <math.h>
#include <stdint.h>

#define TT 256
#define BB 64
#define II 256
#define HH 256
#define NN 8
#define FF 1024   // 4*H

// ---------------- scratch (device globals; no allocs) ----------------
__device__ int   g_flags[TT * NN];
__device__ __nv_bfloat16 g_xh[(size_t)TT * BB * II];     // X hi  [m][k]
__device__ __nv_bfloat16 g_xl[(size_t)TT * BB * II];     // X lo
// h exchange buffers, parity double-buffered: [p][n][b][k] bf16 hi/lo
__device__ __nv_bfloat16 g_hbh[2 * NN * BB * HH];
__device__ __nv_bfloat16 g_hbl[2 * NN * BB * HH];

extern __shared__ char dynsmem[];

// ---------------- helpers ----------------
__device__ __forceinline__ uint32_t smem_u32(const void* p) {
    uint32_t a;
    asm("{ .reg .u64 t; cvta.to.shared.u64 t, %1; cvt.u32.u64 %0, t; }" : "=r"(a) : "l"(p));
    return a;
}

__device__ __forceinline__ void ldsm_x4(uint32_t* r, uint32_t addr) {
    asm volatile("ldmatrix.sync.aligned.m8n8.x4.shared.b16 {%0,%1,%2,%3}, [%4];"
                 : "=r"(r[0]), "=r"(r[1]), "=r"(r[2]), "=r"(r[3]) : "r"(addr));
}

__device__ __forceinline__ void mma_bf16(float* c, const uint32_t* a,
                                         uint32_t b0, uint32_t b1) {
    asm volatile(
        "mma.sync.aligned.m16n8k16.row.col.f32.bf16.bf16.f32 "
        "{%0,%1,%2,%3}, {%4,%5,%6,%7}, {%8,%9}, {%0,%1,%2,%3};"
        : "+f"(c[0]), "+f"(c[1]), "+f"(c[2]), "+f"(c[3])
        : "r"(a[0]), "r"(a[1]), "r"(a[2]), "r"(a[3]), "r"(b0), "r"(b1));
}

__device__ __forceinline__ float fast_sigmoid(float x) {
    return __fdividef(1.f, 1.f + __expf(-x));
}
__device__ __forceinline__ float fast_tanh(float x) {
    return 1.f - __fdividef(2.f, __expf(2.f * x) + 1.f);
}

// ---------------------------------------------------------------------------
// conv_x: split X into bf16 hi/lo. Also zeroes g_flags.
// ---------------------------------------------------------------------------
__global__ __launch_bounds__(256) void conv_x(const float* __restrict__ x) {
    if (blockIdx.x < 8) g_flags[blockIdx.x * 256 + threadIdx.x] = 0;
    const size_t i0 = ((size_t)blockIdx.x * 256 + threadIdx.x) * 4;
    const float4 v = *(const float4*)(x + i0);
    const float f[4] = {v.x, v.y, v.z, v.w};
    __nv_bfloat16 hv[4], lv[4];
#pragma unroll
    for (int j = 0; j < 4; j++) {
        hv[j] = __float2bfloat16(f[j]);
        lv[j] = __float2bfloat16(f[j] - __bfloat162float(hv[j]));
    }
    *reinterpret_cast<uint2*>(g_xh + i0) = *reinterpret_cast<uint2*>(hv);
    *reinterpret_cast<uint2*>(g_xl + i0) = *reinterpret_cast<uint2*>(lv);
}

// ---------------------------------------------------------------------------
// recur_kernel: fully fused persistent LSTM. 128 CTAs (jt, n), 256 threads.
// Per step: z = X(t) @ Wx + h(t-1) @ Wh + bias, all via split-bf16 HMMA with
// fp32 fragment accumulation, then gate/cell/mask epilogue.
// h(t) is published pre-split (bf16 hi/lo) to parity-double-buffered globals,
// so consumers cp.async it directly into the A-tile SMEM.
// c ordering: c = 4*hl + gate  ->  f = gate*H + jt*16 + hl.
// ---------------------------------------------------------------------------
#define WSTR   264                  // bf16 elems per smem row (256 + 8 pad)
#define S_WXH  0
#define S_WXL  33792
#define S_WHH  67584
#define S_WHL  101376
#define S_AH   135168
#define S_AL   168960
#define S_ZS   202752               // 64*68*4 = 17408
#define S_TOT  220160

__device__ __forceinline__ void gemm3_acc(
    float acc[2][2][4], uint32_t sbase,
    uint32_t bH, uint32_t bL,
    int a_row, int a_kof, int b_row, int b_kof)
{
#pragma unroll 4
    for (int ks = 0; ks < 16; ks++) {
        const int k0 = ks * 16;
        uint32_t ah[2][4], al[2][4], bh[4], bl[4];
#pragma unroll
        for (int ma = 0; ma < 2; ma++) {
            ldsm_x4(ah[ma], sbase + S_AH + ((a_row + ma * 16) * WSTR + k0 + a_kof) * 2);
            ldsm_x4(al[ma], sbase + S_AL + ((a_row + ma * 16) * WSTR + k0 + a_kof) * 2);
        }
        ldsm_x4(bh, sbase + bH + (b_row * WSTR + k0 + b_kof) * 2);
        ldsm_x4(bl, sbase + bL + (b_row * WSTR + k0 + b_kof) * 2);
#pragma unroll
        for (int ma = 0; ma < 2; ma++)
#pragma unroll
            for (int nf = 0; nf < 2; nf++) {
                mma_bf16(acc[ma][nf], ah[ma], bh[nf * 2], bh[nf * 2 + 1]);
                mma_bf16(acc[ma][nf], ah[ma], bl[nf * 2], bl[nf * 2 + 1]);
                mma_bf16(acc[ma][nf], al[ma], bh[nf * 2], bh[nf * 2 + 1]);
            }
    }
}

__global__ __launch_bounds__(256, 1) void recur_kernel(
    const float* __restrict__ w,    // [N, I+H, FF]
    const float* __restrict__ bi,   // [N, FF]
    const float* __restrict__ bh_,  // [N, FF]
    const int*   __restrict__ fd,   // [T*B]
    float* out)                     // [T, N, B, H]
{
    char* sm = dynsmem;
    const uint32_t sbase = smem_u32(sm);
    __nv_bfloat16* Wxh = (__nv_bfloat16*)(sm + S_WXH);
    __nv_bfloat16* Wxl = (__nv_bfloat16*)(sm + S_WXL);
    __nv_bfloat16* Whh = (__nv_bfloat16*)(sm + S_WHH);
    __nv_bfloat16* Whl = (__nv_bfloat16*)(sm + S_WHL);
    float* Zs = (float*)(sm + S_ZS);     // [64][68]

    const int jt = blockIdx.x & 15;
    const int n  = blockIdx.x >> 4;
    const int tid = threadIdx.x;
    const int wid = tid >> 5, lane = tid & 31;
    const int tx = tid & 15;
    const int ty = tid >> 4;

    // warp tiling: mw = b-half (32), nw = c-quarter (16)
    const int mw = wid & 1, nw = wid >> 1;
    const int lrow = lane & 7, lgrp = lane >> 3;
    const int a_row = mw * 32 + (lgrp & 1) * 8 + lrow;   // + ma*16
    const int a_kof = (lgrp >> 1) * 8;
    const int b_row = nw * 16 + (lgrp >> 1) * 8 + lrow;
    const int b_kof = (lgrp & 1) * 8;

    // ---- prologue: convert Wx and Wh slices (fp32 -> split bf16, K-major) ----
    const float* wx = w + (size_t)n * (II + HH) * FF;            // k in [0,256)
    const float* wh = wx + (size_t)II * FF;                      // k in [256,512)
    for (int i = tid; i < 64 * 256; i += 256) {
        const int k = i >> 6, q = i & 63;
        const int g = q >> 4, hl = q & 15;
        const int c = 4 * hl + g;
        const size_t col = (size_t)g * HH + jt * 16 + hl;
        {
            const float v = wx[(size_t)k * FF + col];
            const __nv_bfloat16 h = __float2bfloat16(v);
            Wxh[c * WSTR + k] = h;
            Wxl[c * WSTR + k] = __float2bfloat16(v - __bfloat162float(h));
        }
        {
            const float v = wh[(size_t)k * FF + col];
            const __nv_bfloat16 h = __float2bfloat16(v);
            Whh[c * WSTR + k] = h;
            Whl[c * WSTR + k] = __float2bfloat16(v - __bfloat162float(h));
        }
    }

    // bias registers: thread's column j, 4 gates
    const int j = jt * 16 + tx;
    float bias4[4];
#pragma unroll
    for (int g = 0; g < 4; g++)
        bias4[g] = bi[(size_t)n * FF + g * HH + j] + bh_[(size_t)n * FF + g * HH + j];

    float creg[4] = {0.f, 0.f, 0.f, 0.f};

    // A-tile cp.async mapping: id -> row r = id>>5, 16B chunk ch = id&31
    // (row = 256 bf16 = 512 B = 32 chunks; smem row stride 528 B)

    // ---- load X(0) tile and run its x-GEMM ----
    __syncthreads();   // weights visible
    {
#pragma unroll
        for (int i = 0; i < 8; i++) {
            const int id = tid + 256 * i, r = id >> 5, ch = id & 31;
            asm volatile("cp.async.ca.shared.global [%0], [%1], 16;\n"
                         :: "r"(sbase + S_AH + r * 528 + ch * 16),
                            "l"((const void*)(g_xh + (size_t)r * II + ch * 8)));
            asm volatile("cp.async.ca.shared.global [%0], [%1], 16;\n"
                         :: "r"(sbase + S_AL + r * 528 + ch * 16),
                            "l"((const void*)(g_xl + (size_t)r * II + ch * 8)));
        }
        asm volatile("cp.async.commit_group;\n");
        asm volatile("cp.async.wait_group 0;\n" ::: "memory");
    }
    __syncthreads();

    float acc[2][2][4];
#pragma unroll
    for (int ma = 0; ma < 2; ma++)
#pragma unroll
        for (int nf = 0; nf < 2; nf++)
#pragma unroll
            for (int q = 0; q < 4; q++) acc[ma][nf][q] = 0.f;
    gemm3_acc(acc, sbase, S_WXH, S_WXL, a_row, a_kof, b_row, b_kof);

    for (int t = 0; t < TT; t++) {
        if (t > 0) {
            // wait for all 16 CTAs of branch n to publish h(t-1)
            if (tid == 0) {
                int v;
                do {
                    asm volatile("ld.acquire.gpu.global.s32 %0, [%1];"
                                 : "=r"(v) : "l"(g_flags + (t - 1) * NN + n));
                } while (v < 16);
            }
            __syncthreads();   // also guards Ah/Al reuse (x-GEMM done in all warps)

            // cp.async h(t-1) bf16 hi/lo straight into Ah/Al
            const __nv_bfloat16* sh = g_hbh + ((size_t)((t - 1) & 1) * NN + n) * BB * HH;
            const __nv_bfloat16* sl = g_hbl + ((size_t)((t - 1) & 1) * NN + n) * BB * HH;
#pragma unroll
            for (int i = 0; i < 8; i++) {
                const int id = tid + 256 * i, r = id >> 5, ch = id & 31;
                asm volatile("cp.async.ca.shared.global [%0], [%1], 16;\n"
                             :: "r"(sbase + S_AH + r * 528 + ch * 16),
                                "l"((const void*)(sh + (size_t)r * HH + ch * 8)));
                asm volatile("cp.async.ca.shared.global [%0], [%1], 16;\n"
                             :: "r"(sbase + S_AL + r * 528 + ch * 16),
                                "l"((const void*)(sl + (size_t)r * HH + ch * 8)));
            }
            asm volatile("cp.async.commit_group;\n");
            asm volatile("cp.async.wait_group 0;\n" ::: "memory");
            __syncthreads();

            // h-GEMM accumulates on top of the x-part already in acc
            gemm3_acc(acc, sbase, S_WHH, S_WHL, a_row, a_kof, b_row, b_kof);
        }

        // -- stage z fragments into Zs[b][c] --
#pragma unroll
        for (int ma = 0; ma < 2; ma++)
#pragma unroll
            for (int nf = 0; nf < 2; nf++) {
                const int row = mw * 32 + ma * 16 + (lane >> 2);
                const int col = nw * 16 + nf * 8 + (lane & 3) * 2;
                *(float2*)(Zs + row * 68 + col) =
                    make_float2(acc[ma][nf][0], acc[ma][nf][1]);
                *(float2*)(Zs + (row + 8) * 68 + col) =
                    make_float2(acc[ma][nf][2], acc[ma][nf][3]);
            }
        __syncthreads();

        // -- prefetch X(t+1) (Ah/Al free; overlaps epilogue) --
        if (t + 1 < TT) {
            const __nv_bfloat16* xh = g_xh + (size_t)(t + 1) * BB * II;
            const __nv_bfloat16* xl = g_xl + (size_t)(t + 1) * BB * II;
#pragma unroll
            for (int i = 0; i < 8; i++) {
                const int id = tid + 256 * i, r = id >> 5, ch = id & 31;
                asm volatile("cp.async.ca.shared.global [%0], [%1], 16;\n"
                             :: "r"(sbase + S_AH + r * 528 + ch * 16),
                                "l"((const void*)(xh + (size_t)r * II + ch * 8)));
                asm volatile("cp.async.ca.shared.global [%0], [%1], 16;\n"
                             :: "r"(sbase + S_AL + r * 528 + ch * 16),
                                "l"((const void*)(xl + (size_t)r * II + ch * 8)));
            }
            asm volatile("cp.async.commit_group;\n");
        }

        // -- LSTM epilogue; publish h(t) both fp32 (out) and split bf16 --
        __nv_bfloat16* hbh = g_hbh + ((size_t)(t & 1) * NN + n) * BB * HH;
        __nv_bfloat16* hbl = g_hbl + ((size_t)(t & 1) * NN + n) * BB * HH;
        const int4 dur4 = *(const int4*)(fd + t * BB + 4 * ty);
        const int durs[4] = {dur4.x, dur4.y, dur4.z, dur4.w};
#pragma unroll
        for (int r = 0; r < 4; r++) {
            const int b = 4 * ty + r;
            const float4 zh = *(const float4*)(Zs + b * 68 + 4 * tx);  // i,f,o,g
            const float zi  = zh.x + bias4[0];
            const float zf_ = zh.y + bias4[1];
            const float zo  = zh.z + bias4[2];
            const float zg_ = zh.w + bias4[3];

            const bool keep = (n > (durs[r] >> 3));

            const float ig = fast_sigmoid(zi);
            const float fg = fast_sigmoid(zf_);
            const float og = fast_sigmoid(zo);
            const float gg = fast_tanh(zg_);

            float cn = fg * creg[r] + ig * gg;
            cn = keep ? creg[r] : cn;
            creg[r] = cn;
            const float hn = og * fast_tanh(cn);

            out[((size_t)(t * NN + n) * BB + b) * HH + j] = hn;
            const __nv_bfloat16 hh = __float2bfloat16(hn);
            hbh[b * HH + j] = hh;
            hbl[b * HH + j] = __float2bfloat16(hn - __bfloat162float(hh));
        }

        __syncthreads();   // Zs reads done; h stores issued by all threads

        if (tid == 0) {
            asm volatile("red.release.gpu.global.add.s32 [%0], %1;"
                         :: "l"(g_flags + t * NN + n), "r"(1) : "memory");
        }

        // -- x-GEMM for step t+1 (hides in the publish->wait slack) --
        if (t + 1 < TT) {
            asm volatile("cp.async.wait_group 0;\n" ::: "memory");
            __syncthreads();
#pragma unroll
            for (int ma = 0; ma < 2; ma++)
#pragma unroll
                for (int nf = 0; nf < 2; nf++)
#pragma unroll
                    for (int q = 0; q < 4; q++) acc[ma][nf][q] = 0.f;
            gemm3_acc(acc, sbase, S_WXH, S_WXL, a_row, a_kof, b_row, b_kof);
        }
    }
}

// ---------------------------------------------------------------------------
extern "C" void kernel_launch(void* const* d_in, const int* in_sizes, int n_in,
                              void* d_out, int out_size)
{
    const float* x  = (const float*)d_in[0];   // [T,B,I] f32
    const int*   fd = (const int*)  d_in[1];   // [T,B]   i32
    const float* w  = (const float*)d_in[2];   // [N,I+H,4H] f32
    const float* bi = (const float*)d_in[3];   // [N,4H]
    const float* bh = (const float*)d_in[4];   // [N,4H]
    float* out = (float*)d_out;                // [T,N,B,H]

    conv_x<<<4096, 256>>>(x);

    cudaFuncSetAttribute(recur_kernel, cudaFuncAttributeMaxDynamicSharedMemorySize,
                         S_TOT);
    recur_kernel<<<128, 256, S_TOT>>>(w, bi, bh, fd, out);
}

// round 10
// speedup vs baseline: 6.0706x; 1.4289x over previous
#include <cuda_runtime.h>
#include <cuda_fp16.h>
#include <math.h>
#include <stdint.h>

#define TT 256
#define BB 64
#define II 256
#define HH 256
#define NN 8
#define FF 1024   // 4*H

// ---------------- scratch (device globals; no allocs) ----------------
__device__ int g_flags[TT * NN];
__device__ __align__(16) __half g_xf[(size_t)TT * BB * II];   // X fp16 [m][k]
// h exchange, parity double-buffered: [p][n][b][k] fp16
__device__ __align__(16) __half g_hf[2 * NN * BB * HH];

extern __shared__ char dynsmem[];

// ---------------- helpers ----------------
__device__ __forceinline__ uint32_t smem_u32(const void* p) {
    uint32_t a;
    asm("{ .reg .u64 t; cvta.to.shared.u64 t, %1; cvt.u32.u64 %0, t; }" : "=r"(a) : "l"(p));
    return a;
}

__device__ __forceinline__ void ldsm_x4(uint32_t* r, uint32_t addr) {
    asm volatile("ldmatrix.sync.aligned.m8n8.x4.shared.b16 {%0,%1,%2,%3}, [%4];"
                 : "=r"(r[0]), "=r"(r[1]), "=r"(r[2]), "=r"(r[3]) : "r"(addr));
}

__device__ __forceinline__ void mma_f16(float* c, const uint32_t* a,
                                        uint32_t b0, uint32_t b1) {
    asm volatile(
        "mma.sync.aligned.m16n8k16.row.col.f32.f16.f16.f32 "
        "{%0,%1,%2,%3}, {%4,%5,%6,%7}, {%8,%9}, {%0,%1,%2,%3};"
        : "+f"(c[0]), "+f"(c[1]), "+f"(c[2]), "+f"(c[3])
        : "r"(a[0]), "r"(a[1]), "r"(a[2]), "r"(a[3]), "r"(b0), "r"(b1));
}

__device__ __forceinline__ float fast_sigmoid(float x) {
    return __fdividef(1.f, 1.f + __expf(-x));
}
__device__ __forceinline__ float fast_tanh(float x) {
    return 1.f - __fdividef(2.f, __expf(2.f * x) + 1.f);
}

// ---------------------------------------------------------------------------
// conv_x: X fp32 -> fp16. Also zeroes g_flags.
// ---------------------------------------------------------------------------
__global__ __launch_bounds__(256) void conv_x(const float* __restrict__ x) {
    if (blockIdx.x < 8) g_flags[blockIdx.x * 256 + threadIdx.x] = 0;
    const size_t i0 = ((size_t)blockIdx.x * 256 + threadIdx.x) * 4;
    const float4 v = *(const float4*)(x + i0);
    __half hv[4];
    hv[0] = __float2half(v.x); hv[1] = __float2half(v.y);
    hv[2] = __float2half(v.z); hv[3] = __float2half(v.w);
    *reinterpret_cast<uint2*>(g_xf + i0) = *reinterpret_cast<uint2*>(hv);
}

// ---------------------------------------------------------------------------
// recur_kernel: fused persistent LSTM, fp16 2-product HMMA.
// 128 CTAs (jt, n), 256 threads. Per step:
//   z = X(t) @ Wx + h(t-1) @ Wh + bias,   a·w ~= a·wh + a·wl (w fp16 hi/lo)
// SMEM: Wxh/Wxl/Whh/Whl [c=64][k=256] fp16 K-major (resident),
//       XB [64][256] fp16 (X tile, prefetched 1 step ahead),
//       HB [64][256] fp16 (h tile), Zs [64][68] f32 staging.
// c ordering: c = 4*hl + gate  ->  f = gate*H + jt*16 + hl.
// ---------------------------------------------------------------------------
#define WSTR   264                  // fp16 elems per smem row (256 + 8 pad)
#define S_WXH  0
#define S_WXL  33792
#define S_WHH  67584
#define S_WHL  101376
#define S_XB   135168
#define S_HB   168960
#define S_ZS   202752               // 64*68*4 = 17408
#define S_TOT  220160

__device__ __forceinline__ void gemm2_acc(
    float acc[2][2][4], uint32_t sbase, uint32_t aB,
    uint32_t bH, uint32_t bL,
    int a_row, int a_kof, int b_row, int b_kof)
{
#pragma unroll 4
    for (int ks = 0; ks < 16; ks++) {
        const int k0 = ks * 16;
        uint32_t a[2][4], bh[4], bl[4];
#pragma unroll
        for (int ma = 0; ma < 2; ma++)
            ldsm_x4(a[ma], sbase + aB + ((a_row + ma * 16) * WSTR + k0 + a_kof) * 2);
        ldsm_x4(bh, sbase + bH + (b_row * WSTR + k0 + b_kof) * 2);
        ldsm_x4(bl, sbase + bL + (b_row * WSTR + k0 + b_kof) * 2);
#pragma unroll
        for (int ma = 0; ma < 2; ma++)
#pragma unroll
            for (int nf = 0; nf < 2; nf++) {
                mma_f16(acc[ma][nf], a[ma], bh[nf * 2], bh[nf * 2 + 1]);
                mma_f16(acc[ma][nf], a[ma], bl[nf * 2], bl[nf * 2 + 1]);
            }
    }
}

__global__ __launch_bounds__(256, 1) void recur_kernel(
    const float* __restrict__ w,    // [N, I+H, FF]
    const float* __restrict__ bi,   // [N, FF]
    const float* __restrict__ bh_,  // [N, FF]
    const int*   __restrict__ fd,   // [T*B]
    float* out)                     // [T, N, B, H]
{
    char* sm = dynsmem;
    const uint32_t sbase = smem_u32(sm);
    __half* Wxh = (__half*)(sm + S_WXH);
    __half* Wxl = (__half*)(sm + S_WXL);
    __half* Whh = (__half*)(sm + S_WHH);
    __half* Whl = (__half*)(sm + S_WHL);
    float* Zs = (float*)(sm + S_ZS);     // [64][68]

    const int jt = blockIdx.x & 15;
    const int n  = blockIdx.x >> 4;
    const int tid = threadIdx.x;
    const int wid = tid >> 5, lane = tid & 31;
    const int tx = tid & 15;
    const int ty = tid >> 4;

    // warp tiling: mw = b-half (32), nw = c-quarter (16)
    const int mw = wid & 1, nw = wid >> 1;
    const int lrow = lane & 7, lgrp = lane >> 3;
    const int a_row = mw * 32 + (lgrp & 1) * 8 + lrow;   // + ma*16
    const int a_kof = (lgrp >> 1) * 8;
    const int b_row = nw * 16 + (lgrp >> 1) * 8 + lrow;
    const int b_kof = (lgrp & 1) * 8;

    // ---- prologue: convert Wx and Wh slices (fp32 -> fp16 hi/lo, K-major) ----
    const float* wx = w + (size_t)n * (II + HH) * FF;            // k in [0,256)
    const float* wh = wx + (size_t)II * FF;                      // k in [256,512)
    for (int i = tid; i < 64 * 256; i += 256) {
        const int k = i >> 6, q = i & 63;
        const int g = q >> 4, hl = q & 15;
        const int c = 4 * hl + g;
        const size_t col = (size_t)g * HH + jt * 16 + hl;
        {
            const float v = wx[(size_t)k * FF + col];
            const __half h = __float2half(v);
            Wxh[c * WSTR + k] = h;
            Wxl[c * WSTR + k] = __float2half(v - __half2float(h));
        }
        {
            const float v = wh[(size_t)k * FF + col];
            const __half h = __float2half(v);
            Whh[c * WSTR + k] = h;
            Whl[c * WSTR + k] = __float2half(v - __half2float(h));
        }
    }

    // bias registers: thread's column j, 4 gates
    const int j = jt * 16 + tx;
    float bias4[4];
#pragma unroll
    for (int g = 0; g < 4; g++)
        bias4[g] = bi[(size_t)n * FF + g * HH + j] + bh_[(size_t)n * FF + g * HH + j];

    float creg[4] = {0.f, 0.f, 0.f, 0.f};

    // A-tile cp.async mapping: id -> row r = id>>5, 16B chunk ch = id&31
    // (row = 256 fp16 = 512 B = 32 chunks; smem row stride 528 B)

    // ---- load X(0) tile and run its x-GEMM ----
    __syncthreads();   // weights visible
    {
#pragma unroll
        for (int i = 0; i < 8; i++) {
            const int id = tid + 256 * i, r = id >> 5, ch = id & 31;
            asm volatile("cp.async.ca.shared.global [%0], [%1], 16;\n"
                         :: "r"(sbase + S_XB + r * 528 + ch * 16),
                            "l"((const void*)(g_xf + (size_t)r * II + ch * 8)));
        }
        asm volatile("cp.async.commit_group;\n");
        asm volatile("cp.async.wait_group 0;\n" ::: "memory");
    }
    __syncthreads();

    float acc[2][2][4];
#pragma unroll
    for (int ma = 0; ma < 2; ma++)
#pragma unroll
        for (int nf = 0; nf < 2; nf++)
#pragma unroll
            for (int q = 0; q < 4; q++) acc[ma][nf][q] = 0.f;
    gemm2_acc(acc, sbase, S_XB, S_WXH, S_WXL, a_row, a_kof, b_row, b_kof);

    for (int t = 0; t < TT; t++) {
        if (t > 0) {
            // all threads spin on the branch flag (no barrier needed after)
            int v;
            do {
                asm volatile("ld.acquire.gpu.global.s32 %0, [%1];"
                             : "=r"(v) : "l"(g_flags + (t - 1) * NN + n));
            } while (v < 16);

            // cp.async h(t-1) fp16 straight into HB
            const __half* sh = g_hf + ((size_t)((t - 1) & 1) * NN + n) * BB * HH;
#pragma unroll
            for (int i = 0; i < 8; i++) {
                const int id = tid + 256 * i, r = id >> 5, ch = id & 31;
                asm volatile("cp.async.ca.shared.global [%0], [%1], 16;\n"
                             :: "r"(sbase + S_HB + r * 528 + ch * 16),
                                "l"((const void*)(sh + (size_t)r * HH + ch * 8)));
            }
            asm volatile("cp.async.commit_group;\n");
            asm volatile("cp.async.wait_group 0;\n" ::: "memory");
            __syncthreads();

            // h-GEMM accumulates on top of the x-part already in acc
            gemm2_acc(acc, sbase, S_HB, S_WHH, S_WHL, a_row, a_kof, b_row, b_kof);
        }

        // -- stage z fragments into Zs[b][c] --
#pragma unroll
        for (int ma = 0; ma < 2; ma++)
#pragma unroll
            for (int nf = 0; nf < 2; nf++) {
                const int row = mw * 32 + ma * 16 + (lane >> 2);
                const int col = nw * 16 + nf * 8 + (lane & 3) * 2;
                *(float2*)(Zs + row * 68 + col) =
                    make_float2(acc[ma][nf][0], acc[ma][nf][1]);
                *(float2*)(Zs + (row + 8) * 68 + col) =
                    make_float2(acc[ma][nf][2], acc[ma][nf][3]);
            }
        __syncthreads();

        // -- prefetch X(t+1) into XB (XB free since last x-GEMM; overlaps epi) --
        if (t + 1 < TT) {
            const __half* xs = g_xf + (size_t)(t + 1) * BB * II;
#pragma unroll
            for (int i = 0; i < 8; i++) {
                const int id = tid + 256 * i, r = id >> 5, ch = id & 31;
                asm volatile("cp.async.ca.shared.global [%0], [%1], 16;\n"
                             :: "r"(sbase + S_XB + r * 528 + ch * 16),
                                "l"((const void*)(xs + (size_t)r * II + ch * 8)));
            }
            asm volatile("cp.async.commit_group;\n");
        }

        // -- LSTM epilogue; publish h(t) fp32 (out) + fp16 (exchange) --
        __half* hb = g_hf + ((size_t)(t & 1) * NN + n) * BB * HH;
        const int4 dur4 = *(const int4*)(fd + t * BB + 4 * ty);
        const int durs[4] = {dur4.x, dur4.y, dur4.z, dur4.w};
#pragma unroll
        for (int r = 0; r < 4; r++) {
            const int b = 4 * ty + r;
            const float4 zh = *(const float4*)(Zs + b * 68 + 4 * tx);  // i,f,o,g
            const float zi  = zh.x + bias4[0];
            const float zf_ = zh.y + bias4[1];
            const float zo  = zh.z + bias4[2];
            const float zg_ = zh.w + bias4[3];

            const bool keep = (n > (durs[r] >> 3));

            const float ig = fast_sigmoid(zi);
            const float fg = fast_sigmoid(zf_);
            const float og = fast_sigmoid(zo);
            const float gg = fast_tanh(zg_);

            float cn = fg * creg[r] + ig * gg;
            cn = keep ? creg[r] : cn;
            creg[r] = cn;
            const float hn = og * fast_tanh(cn);

            out[((size_t)(t * NN + n) * BB + b) * HH + j] = hn;
            hb[b * HH + j] = __float2half(hn);
        }

        __syncthreads();   // Zs reads done; h stores issued by all threads

        if (tid == 0) {
            asm volatile("red.release.gpu.global.add.s32 [%0], %1;"
                         :: "l"(g_flags + t * NN + n), "r"(1) : "memory");
        }

        // -- x-GEMM for step t+1 (X(t+1) prefetch issued before epilogue) --
        if (t + 1 < TT) {
            asm volatile("cp.async.wait_group 0;\n" ::: "memory");
            __syncthreads();
#pragma unroll
            for (int ma = 0; ma < 2; ma++)
#pragma unroll
                for (int nf = 0; nf < 2; nf++)
#pragma unroll
                    for (int q = 0; q < 4; q++) acc[ma][nf][q] = 0.f;
            gemm2_acc(acc, sbase, S_XB, S_WXH, S_WXL, a_row, a_kof, b_row, b_kof);
        }
    }
}

// ---------------------------------------------------------------------------
extern "C" void kernel_launch(void* const* d_in, const int* in_sizes, int n_in,
                              void* d_out, int out_size)
{
    const float* x  = (const float*)d_in[0];   // [T,B,I] f32
    const int*   fd = (const int*)  d_in[1];   // [T,B]   i32
    const float* w  = (const float*)d_in[2];   // [N,I+H,4H] f32
    const float* bi = (const float*)d_in[3];   // [N,4H]
    const float* bh = (const float*)d_in[4];   // [N,4H]
    float* out = (float*)d_out;                // [T,N,B,H]

    conv_x<<<4096, 256>>>(x);

    cudaFuncSetAttribute(recur_kernel, cudaFuncAttributeMaxDynamicSharedMemorySize,
                         S_TOT);
    recur_kernel<<<128, 256, S_TOT>>>(w, bi, bh, fd, out);
}